// round 9
// baseline (speedup 1.0000x reference)
#include <cuda_runtime.h>
#include <cuda_fp16.h>
#include <math.h>
#include <stdint.h>

#define BATCH 4
#define SEQ   2048
#define DIM   2048
#define NHEAD 16
#define HD    128
#define MROWS (BATCH*SEQ)   // 8192

// ---------------- scratch (static device globals) ----------------
__device__ float g_q[(size_t)MROWS * DIM];
__device__ float g_k[(size_t)MROWS * DIM];
__device__ float g_v[(size_t)MROWS * DIM];
__device__ __half g_xh[(size_t)MROWS * DIM];
__device__ __half g_xl[(size_t)MROWS * DIM];
__device__ __half g_ah[(size_t)MROWS * DIM];
__device__ __half g_al[(size_t)MROWS * DIM];
__device__ __half g_w16[4][(size_t)DIM * DIM];
__device__ __half g_qh[(size_t)MROWS * DIM];
__device__ __half g_ql[(size_t)MROWS * DIM];
__device__ __half g_kh[(size_t)MROWS * DIM];
__device__ __half g_vh[(size_t)MROWS * DIM];

// ---------------- low-level helpers ----------------
__device__ __forceinline__ uint32_t smem_u32(const void* p) {
    uint32_t a;
    asm("{ .reg .u64 t; cvta.to.shared.u64 t, %1; cvt.u32.u64 %0, t; }" : "=r"(a) : "l"(p));
    return a;
}
__device__ __forceinline__ void cp_async16(uint32_t s, const void* g) {
    asm volatile("cp.async.cg.shared.global [%0], [%1], 16;" :: "r"(s), "l"(g));
}
#define CP_COMMIT()  asm volatile("cp.async.commit_group;" ::: "memory")
#define CP_WAIT(n)   asm volatile("cp.async.wait_group %0;" :: "n"(n) : "memory")

__device__ __forceinline__ void ldsm4(uint32_t* r, uint32_t addr) {
    asm volatile("ldmatrix.sync.aligned.m8n8.x4.shared.b16 {%0,%1,%2,%3}, [%4];"
                 : "=r"(r[0]), "=r"(r[1]), "=r"(r[2]), "=r"(r[3]) : "r"(addr));
}
// fp32-accumulate HMMA
__device__ __forceinline__ void mma_f16(float* d, const uint32_t* a, uint32_t b0, uint32_t b1) {
    asm volatile(
        "mma.sync.aligned.m16n8k16.row.col.f32.f16.f16.f32 "
        "{%0,%1,%2,%3}, {%4,%5,%6,%7}, {%8,%9}, {%0,%1,%2,%3};"
        : "+f"(d[0]), "+f"(d[1]), "+f"(d[2]), "+f"(d[3])
        : "r"(a[0]), "r"(a[1]), "r"(a[2]), "r"(a[3]), "r"(b0), "r"(b1));
}
// fp16-accumulate HMMA (lo passes; values ~2^-12 of main sum)
__device__ __forceinline__ void mma_f16h(uint32_t* d, const uint32_t* a, uint32_t b0, uint32_t b1) {
    asm volatile(
        "mma.sync.aligned.m16n8k16.row.col.f16.f16.f16.f16 "
        "{%0,%1}, {%2,%3,%4,%5}, {%6,%7}, {%0,%1};"
        : "+r"(d[0]), "+r"(d[1])
        : "r"(a[0]), "r"(a[1]), "r"(a[2]), "r"(a[3]), "r"(b0), "r"(b1));
}

// ---------------------------------------------------------------------------
// fp32 -> fp16 (hi,lo) split.
// ---------------------------------------------------------------------------
__global__ __launch_bounds__(256)
void split16_kernel(const float* __restrict__ src, __half* __restrict__ hi,
                    __half* __restrict__ lo, int n4)
{
    int i = blockIdx.x * blockDim.x + threadIdx.x;
    if (i >= n4) return;
    float4 x = ((const float4*)src)[i];
    __half h0 = __float2half(x.x), h1 = __float2half(x.y);
    __half h2 = __float2half(x.z), h3 = __float2half(x.w);
    __half2 H0; H0.x = h0; H0.y = h1;
    __half2 H1; H1.x = h2; H1.y = h3;
    ((__half2*)hi)[i*2]   = H0;
    ((__half2*)hi)[i*2+1] = H1;
    __half2 L0, L1;
    L0.x = __float2half(x.x - __half2float(h0));
    L0.y = __float2half(x.y - __half2float(h1));
    L1.x = __float2half(x.z - __half2float(h2));
    L1.y = __float2half(x.w - __half2float(h3));
    ((__half2*)lo)[i*2]   = L0;
    ((__half2*)lo)[i*2+1] = L1;
}

// fp32 -> fp16 round only
__global__ __launch_bounds__(256)
void cvt16_kernel(const float* __restrict__ src, __half* __restrict__ dst, int n4)
{
    int i = blockIdx.x * blockDim.x + threadIdx.x;
    if (i >= n4) return;
    float4 x = ((const float4*)src)[i];
    __half2 H0; H0.x = __float2half(x.x); H0.y = __float2half(x.y);
    __half2 H1; H1.x = __float2half(x.z); H1.y = __float2half(x.w);
    ((__half2*)dst)[i*2]   = H0;
    ((__half2*)dst)[i*2+1] = H1;
}

// ---------------------------------------------------------------------------
// Fused RoPE + fp16 split (Q path)
// ---------------------------------------------------------------------------
__global__ __launch_bounds__(256)
void rope_split16_kernel(const float* __restrict__ src,
                         __half* __restrict__ hi, __half* __restrict__ lo)
{
    int idx = blockIdx.x * blockDim.x + threadIdx.x;
    int i = idx & 63;
    int h = (idx >> 6) & (NHEAD - 1);
    int s = (idx >> 10) & (SEQ - 1);
    int b = idx >> 21;

    float inv = expf(-9.210340371976184f * ((float)i * (1.0f / 64.0f)));
    float ang = (float)s * inv;
    float c, sn;
    sincosf(ang, &sn, &c);

    size_t base = (size_t)(b * SEQ + s) * DIM + h * HD;
    float t1 = src[base + i];
    float t2 = src[base + i + 64];
    float o1 = t1 * c - t2 * sn;
    float o2 = t2 * c + t1 * sn;

    __half h1 = __float2half(o1);
    __half h2 = __float2half(o2);
    hi[base + i]      = h1;
    hi[base + i + 64] = h2;
    lo[base + i]      = __float2half(o1 - __half2float(h1));
    lo[base + i + 64] = __float2half(o2 - __half2float(h2));
}

// Fused RoPE + fp16 round (K path, single plane)
__global__ __launch_bounds__(256)
void rope_cvt16_kernel(const float* __restrict__ src, __half* __restrict__ dst)
{
    int idx = blockIdx.x * blockDim.x + threadIdx.x;
    int i = idx & 63;
    int h = (idx >> 6) & (NHEAD - 1);
    int s = (idx >> 10) & (SEQ - 1);
    int b = idx >> 21;

    float inv = expf(-9.210340371976184f * ((float)i * (1.0f / 64.0f)));
    float ang = (float)s * inv;
    float c, sn;
    sincosf(ang, &sn, &c);

    size_t base = (size_t)(b * SEQ + s) * DIM + h * HD;
    float t1 = src[base + i];
    float t2 = src[base + i + 64];
    dst[base + i]      = __float2half(t1 * c - t2 * sn);
    dst[base + i + 64] = __float2half(t2 * c + t1 * sn);
}

// ---------------------------------------------------------------------------
// fp16 2-pass GEMM: hi pass fp32-acc, lo pass fp16-acc.
// ---------------------------------------------------------------------------
#define GBK       32
#define ROW_B     80
#define PLANE_B   (128 * ROW_B)        // 10240
#define STAGE_B   (3 * PLANE_B)        // 30720 (Ah, Al, Bh)
#define NSTAGE    3
#define GSMEM     (NSTAGE * STAGE_B)   // 92160

__device__ __forceinline__ void load_stage(uint32_t st_u32,
    const __half* __restrict__ Ah, const __half* __restrict__ Al,
    const __half* __restrict__ Bh,
    int m0, int n0, int K, int kc, int tid)
{
#pragma unroll
    for (int p = 0; p < 3; p++) {
        const __half* src = (p == 0) ? Ah : (p == 1) ? Al : Bh;
        const int rbase = (p < 2) ? m0 : n0;
#pragma unroll
        for (int i = 0; i < 2; i++) {
            int idx = i * 256 + tid;
            int r = idx >> 2, c = idx & 3;
            const void* g = src + (size_t)(rbase + r) * K + kc + c * 8;
            cp_async16(st_u32 + p * PLANE_B + r * ROW_B + c * 16, g);
        }
    }
}

__global__ __launch_bounds__(256, 1)
void gemm_mma_kernel(const __half* __restrict__ Ah, const __half* __restrict__ Al,
                     const __half* __restrict__ Bh,
                     const float* __restrict__ bias, float* __restrict__ C,
                     int M, int N, int K)
{
    extern __shared__ char smem[];
    const uint32_t sm0 = smem_u32(smem);
    const int tid  = threadIdx.x;
    const int wid  = tid >> 5;
    const int lane = tid & 31;
    const int wm   = wid & 3;
    const int wn   = wid >> 2;
    const int m0 = blockIdx.y * 128;
    const int n0 = blockIdx.x * 128;
    const int nchunk = K / GBK;

    float acc[2][8][4];
    uint32_t accl[2][8][2];
#pragma unroll
    for (int mt = 0; mt < 2; mt++)
#pragma unroll
        for (int nt = 0; nt < 8; nt++) {
#pragma unroll
            for (int q = 0; q < 4; q++) acc[mt][nt][q] = 0.f;
            accl[mt][nt][0] = 0u; accl[mt][nt][1] = 0u;
        }

    const int lrow  = lane & 15;
    const int lkoff = (lane >> 4) * 16;

    load_stage(sm0,           Ah, Al, Bh, m0, n0, K, 0,   tid);
    CP_COMMIT();
    load_stage(sm0 + STAGE_B, Ah, Al, Bh, m0, n0, K, GBK, tid);
    CP_COMMIT();

    for (int i = 0; i < nchunk; i++) {
        CP_WAIT(1);
        __syncthreads();

        if (i + 2 < nchunk)
            load_stage(sm0 + ((i + 2) % NSTAGE) * STAGE_B,
                       Ah, Al, Bh, m0, n0, K, (i + 2) * GBK, tid);
        CP_COMMIT();

        const uint32_t st = sm0 + (i % NSTAGE) * STAGE_B;
        const uint32_t aRow = st + (wm * 32 + lrow) * ROW_B + lkoff;
        const uint32_t bRow = st + 2 * PLANE_B + (wn * 64 + lrow) * ROW_B + lkoff;

#pragma unroll
        for (int ks = 0; ks < 2; ks++) {
            uint32_t ah[2][4], al[2][4], bh[4][4];
#pragma unroll
            for (int mt = 0; mt < 2; mt++) {
                ldsm4(ah[mt], aRow           + mt * (16 * ROW_B) + ks * 32);
                ldsm4(al[mt], aRow + PLANE_B + mt * (16 * ROW_B) + ks * 32);
            }
#pragma unroll
            for (int np = 0; np < 4; np++)
                ldsm4(bh[np], bRow + np * (16 * ROW_B) + ks * 32);
#pragma unroll
            for (int mt = 0; mt < 2; mt++)
#pragma unroll
                for (int nt = 0; nt < 8; nt++) {
                    const int np = nt >> 1, h = nt & 1;
                    mma_f16(acc[mt][nt],   ah[mt], bh[np][h], bh[np][2 + h]);
                    mma_f16h(accl[mt][nt], al[mt], bh[np][h], bh[np][2 + h]);
                }
        }
        __syncthreads();
    }

    const int grp = lane >> 2;
    const int tig = lane & 3;
#pragma unroll
    for (int mt = 0; mt < 2; mt++) {
        const int rbase = m0 + wm * 32 + mt * 16 + grp;
#pragma unroll
        for (int nt = 0; nt < 8; nt++) {
            const int col = n0 + wn * 64 + nt * 8 + tig * 2;
            float bx = 0.f, by = 0.f;
            if (bias) { bx = bias[col]; by = bias[col + 1]; }
            float2 lo01 = __half22float2(*(__half2*)&accl[mt][nt][0]);
            float2 lo23 = __half22float2(*(__half2*)&accl[mt][nt][1]);
            float2 v0; v0.x = acc[mt][nt][0] + lo01.x + bx; v0.y = acc[mt][nt][1] + lo01.y + by;
            float2 v1; v1.x = acc[mt][nt][2] + lo23.x + bx; v1.y = acc[mt][nt][3] + lo23.y + by;
            *(float2*)(C + (size_t)rbase * N + col)       = v0;
            *(float2*)(C + (size_t)(rbase + 8) * N + col) = v1;
        }
    }
}

// ---------------------------------------------------------------------------
// Causal flash attention, fp16 2-pass; lo passes use fp16 accumulators.
// ---------------------------------------------------------------------------
#define SKB 272
#define SVB 144
#define AQH 0
#define AQL (AQH + 128*SKB)
#define AKH (AQL + 128*SKB)
#define AVT (AKH + 64*SKB)
#define ASMEM (AVT + 128*SVB)   // 105472

__global__ __launch_bounds__(256, 1)
void attn_mma_kernel(const __half* __restrict__ Qh, const __half* __restrict__ Ql,
                     const __half* __restrict__ Kh, const __half* __restrict__ Vh,
                     __half* __restrict__ Ohi, __half* __restrict__ Olo)
{
    extern __shared__ char smem[];
    const uint32_t s0 = smem_u32(smem);
    const int tid  = threadIdx.x;
    const int w    = tid >> 5;
    const int lane = tid & 31;
    const int grp  = lane >> 2;
    const int tig  = lane & 3;
    const int lrow  = lane & 15;
    const int lkoff = (lane >> 4) * 16;

    const int bh = blockIdx.y;
    const int b  = bh >> 4;
    const int h  = bh & (NHEAD - 1);
    const int qt = blockIdx.x;
    const int q0 = qt * 128;

    const size_t rowQ = (size_t)(b * SEQ + q0);
    const __half* qh_g = Qh + rowQ * DIM + h * HD;
    const __half* ql_g = Ql + rowQ * DIM + h * HD;

#pragma unroll
    for (int u = 0; u < 8; u++) {
        int idx = u * 256 + tid;
        int r = idx >> 4, c = idx & 15;
        cp_async16(s0 + AQH + r * SKB + c * 16, qh_g + (size_t)r * DIM + c * 8);
        cp_async16(s0 + AQL + r * SKB + c * 16, ql_g + (size_t)r * DIM + c * 8);
    }
    CP_COMMIT();

    float m[2] = {-1e30f, -1e30f};
    float l[2] = {0.f, 0.f};
    float Oa[16][4];
    uint32_t Ol[16][2];
#pragma unroll
    for (int nt = 0; nt < 16; nt++) {
#pragma unroll
        for (int q = 0; q < 4; q++) Oa[nt][q] = 0.f;
        Ol[nt][0] = 0u; Ol[nt][1] = 0u;
    }

    const float scale = 0.08838834764831845f;
    const int nkt = 2 * qt + 2;

    for (int kt = 0; kt < nkt; kt++) {
        const int kv0 = kt * 64;
        const size_t rowK = (size_t)(b * SEQ + kv0);
        const __half* kh_g = Kh + rowK * DIM + h * HD;
        const __half* vh_g = Vh + rowK * DIM + h * HD;

        __syncthreads();

#pragma unroll
        for (int u = 0; u < 4; u++) {
            int idx = u * 256 + tid;
            int r = idx >> 4, c = idx & 15;
            cp_async16(s0 + AKH + r * SKB + c * 16, kh_g + (size_t)r * DIM + c * 8);
        }
        CP_COMMIT();

#pragma unroll
        for (int u = 0; u < 4; u++) {
            int idx = u * 256 + tid;
            int kv = idx & 63, c = idx >> 6;
            uint4 xh = *(const uint4*)(vh_g + (size_t)kv * DIM + c * 8);
            const uint16_t* uh = (const uint16_t*)&xh;
#pragma unroll
            for (int j = 0; j < 8; j++)
                *(uint16_t*)(smem + AVT + (c * 8 + j) * SVB + kv * 2) = uh[j];
        }
        CP_WAIT(0);
        __syncthreads();

        // ---- S = Q K^T: hi fp32-acc, lo fp16-acc ----
        float Sa[8][4];
        uint32_t Sl[8][2];
#pragma unroll
        for (int j = 0; j < 8; j++) {
#pragma unroll
            for (int q = 0; q < 4; q++) Sa[j][q] = 0.f;
            Sl[j][0] = 0u; Sl[j][1] = 0u;
        }

        const uint32_t aBase = s0 + (w * 16 + lrow) * SKB + lkoff;
        const uint32_t kBase = s0 + lrow * SKB + lkoff;
#pragma unroll
        for (int ks = 0; ks < 8; ks++) {
            uint32_t ah[4], al[4];
            ldsm4(ah, aBase + AQH + ks * 32);
            ldsm4(al, aBase + AQL + ks * 32);
#pragma unroll
            for (int p = 0; p < 4; p++) {
                uint32_t kb[4];
                ldsm4(kb, kBase + AKH + p * 16 * SKB + ks * 32);
                mma_f16(Sa[2*p],    ah, kb[0], kb[2]);
                mma_f16(Sa[2*p+1],  ah, kb[1], kb[3]);
                mma_f16h(Sl[2*p],   al, kb[0], kb[2]);
                mma_f16h(Sl[2*p+1], al, kb[1], kb[3]);
            }
        }
        // merge lo accumulators
#pragma unroll
        for (int j = 0; j < 8; j++) {
            float2 a01 = __half22float2(*(__half2*)&Sl[j][0]);
            float2 a23 = __half22float2(*(__half2*)&Sl[j][1]);
            Sa[j][0] += a01.x; Sa[j][1] += a01.y;
            Sa[j][2] += a23.x; Sa[j][3] += a23.y;
        }

        // ---- scale + causal mask ----
        const int r0g = q0 + w * 16 + grp;
        const int r1g = r0g + 8;
        const bool need_mask = (kt >= 2 * qt);
#pragma unroll
        for (int j = 0; j < 8; j++) {
            const int c0 = kv0 + j * 8 + tig * 2;
            Sa[j][0] *= scale; Sa[j][1] *= scale;
            Sa[j][2] *= scale; Sa[j][3] *= scale;
            if (need_mask) {
                if (c0     > r0g) Sa[j][0] = -1e9f;
                if (c0 + 1 > r0g) Sa[j][1] = -1e9f;
                if (c0     > r1g) Sa[j][2] = -1e9f;
                if (c0 + 1 > r1g) Sa[j][3] = -1e9f;
            }
        }

        // ---- online softmax ----
        float mx0 = -1e30f, mx1 = -1e30f;
#pragma unroll
        for (int j = 0; j < 8; j++) {
            mx0 = fmaxf(mx0, fmaxf(Sa[j][0], Sa[j][1]));
            mx1 = fmaxf(mx1, fmaxf(Sa[j][2], Sa[j][3]));
        }
        mx0 = fmaxf(mx0, __shfl_xor_sync(0xffffffff, mx0, 1));
        mx0 = fmaxf(mx0, __shfl_xor_sync(0xffffffff, mx0, 2));
        mx1 = fmaxf(mx1, __shfl_xor_sync(0xffffffff, mx1, 1));
        mx1 = fmaxf(mx1, __shfl_xor_sync(0xffffffff, mx1, 2));

        const float mn0 = fmaxf(m[0], mx0);
        const float mn1 = fmaxf(m[1], mx1);
        const float alpha0 = __expf(m[0] - mn0);
        const float alpha1 = __expf(m[1] - mn1);
        m[0] = mn0; m[1] = mn1;

        float sum0 = 0.f, sum1 = 0.f;
#pragma unroll
        for (int j = 0; j < 8; j++) {
            Sa[j][0] = __expf(Sa[j][0] - mn0);
            Sa[j][1] = __expf(Sa[j][1] - mn0);
            Sa[j][2] = __expf(Sa[j][2] - mn1);
            Sa[j][3] = __expf(Sa[j][3] - mn1);
            sum0 += Sa[j][0] + Sa[j][1];
            sum1 += Sa[j][2] + Sa[j][3];
        }
        sum0 += __shfl_xor_sync(0xffffffff, sum0, 1);
        sum0 += __shfl_xor_sync(0xffffffff, sum0, 2);
        sum1 += __shfl_xor_sync(0xffffffff, sum1, 1);
        sum1 += __shfl_xor_sync(0xffffffff, sum1, 2);
        l[0] = l[0] * alpha0 + sum0;
        l[1] = l[1] * alpha1 + sum1;

        const __half2 a0h = __float2half2_rn(alpha0);
        const __half2 a1h = __float2half2_rn(alpha1);
#pragma unroll
        for (int nt = 0; nt < 16; nt++) {
            Oa[nt][0] *= alpha0; Oa[nt][1] *= alpha0;
            Oa[nt][2] *= alpha1; Oa[nt][3] *= alpha1;
            *(__half2*)&Ol[nt][0] = __hmul2(*(__half2*)&Ol[nt][0], a0h);
            *(__half2*)&Ol[nt][1] = __hmul2(*(__half2*)&Ol[nt][1], a1h);
        }

        // ---- P V: hi fp32-acc, lo fp16-acc ----
        const uint32_t vBase = s0 + lrow * SVB + lkoff;
#pragma unroll
        for (int ks = 0; ks < 4; ks++) {
            uint32_t ph[4], pl[4];
#pragma unroll
            for (int hf = 0; hf < 2; hf++) {
                const int j = 2 * ks + hf;
                __half2 h01 = __floats2half2_rn(Sa[j][0], Sa[j][1]);
                __half2 h23 = __floats2half2_rn(Sa[j][2], Sa[j][3]);
                ph[2*hf]     = *(uint32_t*)&h01;
                ph[2*hf + 1] = *(uint32_t*)&h23;
                __half2 l01 = __floats2half2_rn(Sa[j][0] - __half2float(h01.x),
                                                Sa[j][1] - __half2float(h01.y));
                __half2 l23 = __floats2half2_rn(Sa[j][2] - __half2float(h23.x),
                                                Sa[j][3] - __half2float(h23.y));
                pl[2*hf]     = *(uint32_t*)&l01;
                pl[2*hf + 1] = *(uint32_t*)&l23;
            }
#pragma unroll
            for (int nb = 0; nb < 8; nb++) {
                uint32_t vb[4];
                ldsm4(vb, vBase + AVT + nb * 16 * SVB + ks * 32);
                mma_f16(Oa[2*nb],    ph, vb[0], vb[2]);
                mma_f16(Oa[2*nb+1],  ph, vb[1], vb[3]);
                mma_f16h(Ol[2*nb],   pl, vb[0], vb[2]);
                mma_f16h(Ol[2*nb+1], pl, vb[1], vb[3]);
            }
        }
    }

    // ---- epilogue: merge lo acc, normalize, write fp16 hi/lo planes ----
    const float invl0 = 1.f / l[0];
    const float invl1 = 1.f / l[1];
    const int r0g = q0 + w * 16 + grp;
    const size_t row0 = (size_t)(b * SEQ + r0g) * DIM + h * HD;
    const size_t row1 = row0 + (size_t)8 * DIM;
#pragma unroll
    for (int nt = 0; nt < 16; nt++) {
        const int col = nt * 8 + tig * 2;
        float2 lo01 = __half22float2(*(__half2*)&Ol[nt][0]);
        float2 lo23 = __half22float2(*(__half2*)&Ol[nt][1]);
        float o0 = (Oa[nt][0] + lo01.x) * invl0, o1 = (Oa[nt][1] + lo01.y) * invl0;
        float o2 = (Oa[nt][2] + lo23.x) * invl1, o3 = (Oa[nt][3] + lo23.y) * invl1;
        __half2 h01 = __floats2half2_rn(o0, o1);
        __half2 h23 = __floats2half2_rn(o2, o3);
        *(__half2*)(Ohi + row0 + col) = h01;
        *(__half2*)(Ohi + row1 + col) = h23;
        __half2 l01 = __floats2half2_rn(o0 - __half2float(h01.x),
                                        o1 - __half2float(h01.y));
        __half2 l23 = __floats2half2_rn(o2 - __half2float(h23.x),
                                        o3 - __half2float(h23.y));
        *(__half2*)(Olo + row0 + col) = l01;
        *(__half2*)(Olo + row1 + col) = l23;
    }
}

// ---------------------------------------------------------------------------
extern "C" void kernel_launch(void* const* d_in, const int* in_sizes, int n_in,
                              void* d_out, int out_size)
{
    (void)in_sizes; (void)n_in; (void)out_size;
    const float* x  = (const float*)d_in[0];
    const float* Wq = (const float*)d_in[1];
    const float* Wk = (const float*)d_in[2];
    const float* Wv = (const float*)d_in[3];
    const float* Wo = (const float*)d_in[4];
    const float* bo = (const float*)d_in[5];
    float* out = (float*)d_out;

    float *q, *k, *v;
    __half *xh, *xl, *ah, *al, *w16, *qh, *ql, *kh, *vh;
    cudaGetSymbolAddress((void**)&q,   g_q);
    cudaGetSymbolAddress((void**)&k,   g_k);
    cudaGetSymbolAddress((void**)&v,   g_v);
    cudaGetSymbolAddress((void**)&xh,  g_xh);
    cudaGetSymbolAddress((void**)&xl,  g_xl);
    cudaGetSymbolAddress((void**)&ah,  g_ah);
    cudaGetSymbolAddress((void**)&al,  g_al);
    cudaGetSymbolAddress((void**)&w16, g_w16);
    cudaGetSymbolAddress((void**)&qh,  g_qh);
    cudaGetSymbolAddress((void**)&ql,  g_ql);
    cudaGetSymbolAddress((void**)&kh,  g_kh);
    cudaGetSymbolAddress((void**)&vh,  g_vh);

    const size_t WSZ = (size_t)DIM * DIM;
    const int nx4 = (MROWS * DIM) / 4;
    const int nw4 = (DIM * DIM) / 4;

    split16_kernel<<<nx4 / 256, 256>>>(x, xh, xl, nx4);
    cvt16_kernel<<<nw4 / 256, 256>>>(Wq, w16 + 0 * WSZ, nw4);
    cvt16_kernel<<<nw4 / 256, 256>>>(Wk, w16 + 1 * WSZ, nw4);
    cvt16_kernel<<<nw4 / 256, 256>>>(Wv, w16 + 2 * WSZ, nw4);
    cvt16_kernel<<<nw4 / 256, 256>>>(Wo, w16 + 3 * WSZ, nw4);

    cudaFuncSetAttribute(gemm_mma_kernel,
                         cudaFuncAttributeMaxDynamicSharedMemorySize, GSMEM);

    dim3 ggrid(DIM / 128, MROWS / 128);
    gemm_mma_kernel<<<ggrid, 256, GSMEM>>>(xh, xl, w16 + 0 * WSZ, nullptr, q, MROWS, DIM, DIM);
    gemm_mma_kernel<<<ggrid, 256, GSMEM>>>(xh, xl, w16 + 1 * WSZ, nullptr, k, MROWS, DIM, DIM);
    gemm_mma_kernel<<<ggrid, 256, GSMEM>>>(xh, xl, w16 + 2 * WSZ, nullptr, v, MROWS, DIM, DIM);

    int rope_threads = BATCH * SEQ * NHEAD * 64;
    rope_split16_kernel<<<rope_threads / 256, 256>>>(q, qh, ql);
    rope_cvt16_kernel<<<rope_threads / 256, 256>>>(k, kh);
    cvt16_kernel<<<nx4 / 256, 256>>>(v, vh, nx4);

    cudaFuncSetAttribute(attn_mma_kernel,
                         cudaFuncAttributeMaxDynamicSharedMemorySize, ASMEM);
    attn_mma_kernel<<<dim3(SEQ / 128, BATCH * NHEAD), 256, ASMEM>>>(
        qh, ql, kh, vh, ah, al);

    gemm_mma_kernel<<<ggrid, 256, GSMEM>>>(ah, al, w16 + 3 * WSZ, bo, out, MROWS, DIM, DIM);
}

// round 10
// speedup vs baseline: 1.3115x; 1.3115x over previous
#include <cuda_runtime.h>
#include <cuda_fp16.h>
#include <math.h>
#include <stdint.h>

#define BATCH 4
#define SEQ   2048
#define DIM   2048
#define NHEAD 16
#define HD    128
#define MROWS (BATCH*SEQ)   // 8192

// ---------------- scratch (static device globals) ----------------
__device__ float g_q[(size_t)MROWS * DIM];
__device__ float g_k[(size_t)MROWS * DIM];
__device__ __half g_xh[(size_t)MROWS * DIM];
__device__ __half g_xl[(size_t)MROWS * DIM];
__device__ __half g_ah[(size_t)MROWS * DIM];
__device__ __half g_w16[4][(size_t)DIM * DIM];
__device__ __half g_qh[(size_t)MROWS * DIM];
__device__ __half g_ql[(size_t)MROWS * DIM];
__device__ __half g_kh[(size_t)MROWS * DIM];
__device__ __half g_vh[(size_t)MROWS * DIM];

// ---------------- low-level helpers ----------------
__device__ __forceinline__ uint32_t smem_u32(const void* p) {
    uint32_t a;
    asm("{ .reg .u64 t; cvta.to.shared.u64 t, %1; cvt.u32.u64 %0, t; }" : "=r"(a) : "l"(p));
    return a;
}
__device__ __forceinline__ void cp_async16(uint32_t s, const void* g) {
    asm volatile("cp.async.cg.shared.global [%0], [%1], 16;" :: "r"(s), "l"(g));
}
#define CP_COMMIT()  asm volatile("cp.async.commit_group;" ::: "memory")
#define CP_WAIT(n)   asm volatile("cp.async.wait_group %0;" :: "n"(n) : "memory")

__device__ __forceinline__ void ldsm4(uint32_t* r, uint32_t addr) {
    asm volatile("ldmatrix.sync.aligned.m8n8.x4.shared.b16 {%0,%1,%2,%3}, [%4];"
                 : "=r"(r[0]), "=r"(r[1]), "=r"(r[2]), "=r"(r[3]) : "r"(addr));
}
__device__ __forceinline__ void mma_f16(float* d, const uint32_t* a, uint32_t b0, uint32_t b1) {
    asm volatile(
        "mma.sync.aligned.m16n8k16.row.col.f32.f16.f16.f32 "
        "{%0,%1,%2,%3}, {%4,%5,%6,%7}, {%8,%9}, {%0,%1,%2,%3};"
        : "+f"(d[0]), "+f"(d[1]), "+f"(d[2]), "+f"(d[3])
        : "r"(a[0]), "r"(a[1]), "r"(a[2]), "r"(a[3]), "r"(b0), "r"(b1));
}

// ---------------------------------------------------------------------------
// fp32 -> fp16 (hi,lo) split.
// ---------------------------------------------------------------------------
__global__ __launch_bounds__(256)
void split16_kernel(const float* __restrict__ src, __half* __restrict__ hi,
                    __half* __restrict__ lo, int n4)
{
    int i = blockIdx.x * blockDim.x + threadIdx.x;
    if (i >= n4) return;
    float4 x = ((const float4*)src)[i];
    __half h0 = __float2half(x.x), h1 = __float2half(x.y);
    __half h2 = __float2half(x.z), h3 = __float2half(x.w);
    __half2 H0; H0.x = h0; H0.y = h1;
    __half2 H1; H1.x = h2; H1.y = h3;
    ((__half2*)hi)[i*2]   = H0;
    ((__half2*)hi)[i*2+1] = H1;
    __half2 L0, L1;
    L0.x = __float2half(x.x - __half2float(h0));
    L0.y = __float2half(x.y - __half2float(h1));
    L1.x = __float2half(x.z - __half2float(h2));
    L1.y = __float2half(x.w - __half2float(h3));
    ((__half2*)lo)[i*2]   = L0;
    ((__half2*)lo)[i*2+1] = L1;
}

// fp32 -> fp16 round only
__global__ __launch_bounds__(256)
void cvt16_kernel(const float* __restrict__ src, __half* __restrict__ dst, int n4)
{
    int i = blockIdx.x * blockDim.x + threadIdx.x;
    if (i >= n4) return;
    float4 x = ((const float4*)src)[i];
    __half2 H0; H0.x = __float2half(x.x); H0.y = __float2half(x.y);
    __half2 H1; H1.x = __float2half(x.z); H1.y = __float2half(x.w);
    ((__half2*)dst)[i*2]   = H0;
    ((__half2*)dst)[i*2+1] = H1;
}

// ---------------------------------------------------------------------------
// Fused RoPE + fp16 split (Q path)
// ---------------------------------------------------------------------------
__global__ __launch_bounds__(256)
void rope_split16_kernel(const float* __restrict__ src,
                         __half* __restrict__ hi, __half* __restrict__ lo)
{
    int idx = blockIdx.x * blockDim.x + threadIdx.x;
    int i = idx & 63;
    int h = (idx >> 6) & (NHEAD - 1);
    int s = (idx >> 10) & (SEQ - 1);
    int b = idx >> 21;

    float inv = expf(-9.210340371976184f * ((float)i * (1.0f / 64.0f)));
    float ang = (float)s * inv;
    float c, sn;
    sincosf(ang, &sn, &c);

    size_t base = (size_t)(b * SEQ + s) * DIM + h * HD;
    float t1 = src[base + i];
    float t2 = src[base + i + 64];
    float o1 = t1 * c - t2 * sn;
    float o2 = t2 * c + t1 * sn;

    __half h1 = __float2half(o1);
    __half h2 = __float2half(o2);
    hi[base + i]      = h1;
    hi[base + i + 64] = h2;
    lo[base + i]      = __float2half(o1 - __half2float(h1));
    lo[base + i + 64] = __float2half(o2 - __half2float(h2));
}

// Fused RoPE + fp16 round (K path, single plane)
__global__ __launch_bounds__(256)
void rope_cvt16_kernel(const float* __restrict__ src, __half* __restrict__ dst)
{
    int idx = blockIdx.x * blockDim.x + threadIdx.x;
    int i = idx & 63;
    int h = (idx >> 6) & (NHEAD - 1);
    int s = (idx >> 10) & (SEQ - 1);
    int b = idx >> 21;

    float inv = expf(-9.210340371976184f * ((float)i * (1.0f / 64.0f)));
    float ang = (float)s * inv;
    float c, sn;
    sincosf(ang, &sn, &c);

    size_t base = (size_t)(b * SEQ + s) * DIM + h * HD;
    float t1 = src[base + i];
    float t2 = src[base + i + 64];
    dst[base + i]      = __float2half(t1 * c - t2 * sn);
    dst[base + i + 64] = __float2half(t2 * c + t1 * sn);
}

// ---------------------------------------------------------------------------
// fp16 GEMM via mma.sync. TWOPASS: A split hi/lo (2 mma passes) or hi only.
// HALFOUT: write fp16 C16 instead of fp32 C.
// CTA tile 128x128, BK=32, 8 warps, 3-stage cp.async pipeline, 2 CTA/SM.
// ---------------------------------------------------------------------------
#define GBK       32
#define ROW_B     80
#define PLANE_B   (128 * ROW_B)        // 10240
#define STAGE_B   (3 * PLANE_B)        // 30720 (Ah, Al, Bh)
#define NSTAGE    3
#define GSMEM     (NSTAGE * STAGE_B)   // 92160

template<bool TWOPASS>
__device__ __forceinline__ void load_stage(uint32_t st_u32,
    const __half* __restrict__ Ah, const __half* __restrict__ Al,
    const __half* __restrict__ Bh,
    int m0, int n0, int K, int kc, int tid)
{
#pragma unroll
    for (int p = 0; p < 3; p++) {
        if (!TWOPASS && p == 1) continue;
        const __half* src = (p == 0) ? Ah : (p == 1) ? Al : Bh;
        const int rbase = (p < 2) ? m0 : n0;
#pragma unroll
        for (int i = 0; i < 2; i++) {
            int idx = i * 256 + tid;
            int r = idx >> 2, c = idx & 3;
            const void* g = src + (size_t)(rbase + r) * K + kc + c * 8;
            cp_async16(st_u32 + p * PLANE_B + r * ROW_B + c * 16, g);
        }
    }
}

template<bool TWOPASS, bool HALFOUT>
__global__ __launch_bounds__(256, 2)
void gemm_mma_kernel(const __half* __restrict__ Ah, const __half* __restrict__ Al,
                     const __half* __restrict__ Bh,
                     const float* __restrict__ bias, float* __restrict__ C,
                     __half* __restrict__ C16,
                     int M, int N, int K)
{
    extern __shared__ char smem[];
    const uint32_t sm0 = smem_u32(smem);
    const int tid  = threadIdx.x;
    const int wid  = tid >> 5;
    const int lane = tid & 31;
    const int wm   = wid & 3;
    const int wn   = wid >> 2;
    const int m0 = blockIdx.y * 128;
    const int n0 = blockIdx.x * 128;
    const int nchunk = K / GBK;

    float acc[2][8][4];
#pragma unroll
    for (int mt = 0; mt < 2; mt++)
#pragma unroll
        for (int nt = 0; nt < 8; nt++)
#pragma unroll
            for (int q = 0; q < 4; q++) acc[mt][nt][q] = 0.f;

    const int lrow  = lane & 15;
    const int lkoff = (lane >> 4) * 16;

    load_stage<TWOPASS>(sm0,           Ah, Al, Bh, m0, n0, K, 0,   tid);
    CP_COMMIT();
    load_stage<TWOPASS>(sm0 + STAGE_B, Ah, Al, Bh, m0, n0, K, GBK, tid);
    CP_COMMIT();

    for (int i = 0; i < nchunk; i++) {
        CP_WAIT(1);
        __syncthreads();

        if (i + 2 < nchunk)
            load_stage<TWOPASS>(sm0 + ((i + 2) % NSTAGE) * STAGE_B,
                                Ah, Al, Bh, m0, n0, K, (i + 2) * GBK, tid);
        CP_COMMIT();

        const uint32_t st = sm0 + (i % NSTAGE) * STAGE_B;
        const uint32_t aRow = st + (wm * 32 + lrow) * ROW_B + lkoff;
        const uint32_t bRow = st + 2 * PLANE_B + (wn * 64 + lrow) * ROW_B + lkoff;

#pragma unroll
        for (int ks = 0; ks < 2; ks++) {
            uint32_t ah[2][4], al[2][4], bh[4][4];
#pragma unroll
            for (int mt = 0; mt < 2; mt++) {
                ldsm4(ah[mt], aRow + mt * (16 * ROW_B) + ks * 32);
                if (TWOPASS)
                    ldsm4(al[mt], aRow + PLANE_B + mt * (16 * ROW_B) + ks * 32);
            }
#pragma unroll
            for (int np = 0; np < 4; np++)
                ldsm4(bh[np], bRow + np * (16 * ROW_B) + ks * 32);
#pragma unroll
            for (int mt = 0; mt < 2; mt++)
#pragma unroll
                for (int nt = 0; nt < 8; nt++) {
                    const int np = nt >> 1, h = nt & 1;
                    mma_f16(acc[mt][nt], ah[mt], bh[np][h], bh[np][2 + h]);
                    if (TWOPASS)
                        mma_f16(acc[mt][nt], al[mt], bh[np][h], bh[np][2 + h]);
                }
        }
        __syncthreads();
    }

    const int grp = lane >> 2;
    const int tig = lane & 3;
#pragma unroll
    for (int mt = 0; mt < 2; mt++) {
        const int rbase = m0 + wm * 32 + mt * 16 + grp;
#pragma unroll
        for (int nt = 0; nt < 8; nt++) {
            const int col = n0 + wn * 64 + nt * 8 + tig * 2;
            float bx = 0.f, by = 0.f;
            if (bias) { bx = bias[col]; by = bias[col + 1]; }
            float v00 = acc[mt][nt][0] + bx, v01 = acc[mt][nt][1] + by;
            float v10 = acc[mt][nt][2] + bx, v11 = acc[mt][nt][3] + by;
            if (HALFOUT) {
                *(__half2*)(C16 + (size_t)rbase * N + col)       = __floats2half2_rn(v00, v01);
                *(__half2*)(C16 + (size_t)(rbase + 8) * N + col) = __floats2half2_rn(v10, v11);
            } else {
                float2 v0; v0.x = v00; v0.y = v01;
                float2 v1; v1.x = v10; v1.y = v11;
                *(float2*)(C + (size_t)rbase * N + col)       = v0;
                *(float2*)(C + (size_t)(rbase + 8) * N + col) = v1;
            }
        }
    }
}

// ---------------------------------------------------------------------------
// Causal flash attention, fp16 2-pass (R7, verified). Writes hi plane only.
// ---------------------------------------------------------------------------
#define SKB 272
#define SVB 144
#define AQH 0
#define AQL (AQH + 128*SKB)
#define AKH (AQL + 128*SKB)
#define AVT (AKH + 64*SKB)
#define ASMEM (AVT + 128*SVB)   // 105472

__global__ __launch_bounds__(256, 1)
void attn_mma_kernel(const __half* __restrict__ Qh, const __half* __restrict__ Ql,
                     const __half* __restrict__ Kh, const __half* __restrict__ Vh,
                     __half* __restrict__ Ohi)
{
    extern __shared__ char smem[];
    const uint32_t s0 = smem_u32(smem);
    const int tid  = threadIdx.x;
    const int w    = tid >> 5;
    const int lane = tid & 31;
    const int grp  = lane >> 2;
    const int tig  = lane & 3;
    const int lrow  = lane & 15;
    const int lkoff = (lane >> 4) * 16;

    const int bh = blockIdx.y;
    const int b  = bh >> 4;
    const int h  = bh & (NHEAD - 1);
    const int qt = blockIdx.x;
    const int q0 = qt * 128;

    const size_t rowQ = (size_t)(b * SEQ + q0);
    const __half* qh_g = Qh + rowQ * DIM + h * HD;
    const __half* ql_g = Ql + rowQ * DIM + h * HD;

#pragma unroll
    for (int u = 0; u < 8; u++) {
        int idx = u * 256 + tid;
        int r = idx >> 4, c = idx & 15;
        cp_async16(s0 + AQH + r * SKB + c * 16, qh_g + (size_t)r * DIM + c * 8);
        cp_async16(s0 + AQL + r * SKB + c * 16, ql_g + (size_t)r * DIM + c * 8);
    }
    CP_COMMIT();

    float m[2] = {-1e30f, -1e30f};
    float l[2] = {0.f, 0.f};
    float Oa[16][4];
#pragma unroll
    for (int nt = 0; nt < 16; nt++)
#pragma unroll
        for (int q = 0; q < 4; q++) Oa[nt][q] = 0.f;

    const float scale = 0.08838834764831845f;
    const int nkt = 2 * qt + 2;

    for (int kt = 0; kt < nkt; kt++) {
        const int kv0 = kt * 64;
        const size_t rowK = (size_t)(b * SEQ + kv0);
        const __half* kh_g = Kh + rowK * DIM + h * HD;
        const __half* vh_g = Vh + rowK * DIM + h * HD;

        __syncthreads();

#pragma unroll
        for (int u = 0; u < 4; u++) {
            int idx = u * 256 + tid;
            int r = idx >> 4, c = idx & 15;
            cp_async16(s0 + AKH + r * SKB + c * 16, kh_g + (size_t)r * DIM + c * 8);
        }
        CP_COMMIT();

#pragma unroll
        for (int u = 0; u < 4; u++) {
            int idx = u * 256 + tid;
            int kv = idx & 63, c = idx >> 6;
            uint4 xh = *(const uint4*)(vh_g + (size_t)kv * DIM + c * 8);
            const uint16_t* uh = (const uint16_t*)&xh;
#pragma unroll
            for (int j = 0; j < 8; j++)
                *(uint16_t*)(smem + AVT + (c * 8 + j) * SVB + kv * 2) = uh[j];
        }
        CP_WAIT(0);
        __syncthreads();

        // ---- S = Q K^T (2-pass fp16) ----
        float Sa[8][4];
#pragma unroll
        for (int j = 0; j < 8; j++)
#pragma unroll
            for (int q = 0; q < 4; q++) Sa[j][q] = 0.f;

        const uint32_t aBase = s0 + (w * 16 + lrow) * SKB + lkoff;
        const uint32_t kBase = s0 + lrow * SKB + lkoff;
#pragma unroll
        for (int ks = 0; ks < 8; ks++) {
            uint32_t ah[4], al[4];
            ldsm4(ah, aBase + AQH + ks * 32);
            ldsm4(al, aBase + AQL + ks * 32);
#pragma unroll
            for (int p = 0; p < 4; p++) {
                uint32_t kb[4];
                ldsm4(kb, kBase + AKH + p * 16 * SKB + ks * 32);
                mma_f16(Sa[2*p],   ah, kb[0], kb[2]);
                mma_f16(Sa[2*p+1], ah, kb[1], kb[3]);
                mma_f16(Sa[2*p],   al, kb[0], kb[2]);
                mma_f16(Sa[2*p+1], al, kb[1], kb[3]);
            }
        }

        // ---- scale + causal mask ----
        const int r0g = q0 + w * 16 + grp;
        const int r1g = r0g + 8;
        const bool need_mask = (kt >= 2 * qt);
#pragma unroll
        for (int j = 0; j < 8; j++) {
            const int c0 = kv0 + j * 8 + tig * 2;
            Sa[j][0] *= scale; Sa[j][1] *= scale;
            Sa[j][2] *= scale; Sa[j][3] *= scale;
            if (need_mask) {
                if (c0     > r0g) Sa[j][0] = -1e9f;
                if (c0 + 1 > r0g) Sa[j][1] = -1e9f;
                if (c0     > r1g) Sa[j][2] = -1e9f;
                if (c0 + 1 > r1g) Sa[j][3] = -1e9f;
            }
        }

        // ---- online softmax ----
        float mx0 = -1e30f, mx1 = -1e30f;
#pragma unroll
        for (int j = 0; j < 8; j++) {
            mx0 = fmaxf(mx0, fmaxf(Sa[j][0], Sa[j][1]));
            mx1 = fmaxf(mx1, fmaxf(Sa[j][2], Sa[j][3]));
        }
        mx0 = fmaxf(mx0, __shfl_xor_sync(0xffffffff, mx0, 1));
        mx0 = fmaxf(mx0, __shfl_xor_sync(0xffffffff, mx0, 2));
        mx1 = fmaxf(mx1, __shfl_xor_sync(0xffffffff, mx1, 1));
        mx1 = fmaxf(mx1, __shfl_xor_sync(0xffffffff, mx1, 2));

        const float mn0 = fmaxf(m[0], mx0);
        const float mn1 = fmaxf(m[1], mx1);
        const float alpha0 = __expf(m[0] - mn0);
        const float alpha1 = __expf(m[1] - mn1);
        m[0] = mn0; m[1] = mn1;

        float sum0 = 0.f, sum1 = 0.f;
#pragma unroll
        for (int j = 0; j < 8; j++) {
            Sa[j][0] = __expf(Sa[j][0] - mn0);
            Sa[j][1] = __expf(Sa[j][1] - mn0);
            Sa[j][2] = __expf(Sa[j][2] - mn1);
            Sa[j][3] = __expf(Sa[j][3] - mn1);
            sum0 += Sa[j][0] + Sa[j][1];
            sum1 += Sa[j][2] + Sa[j][3];
        }
        sum0 += __shfl_xor_sync(0xffffffff, sum0, 1);
        sum0 += __shfl_xor_sync(0xffffffff, sum0, 2);
        sum1 += __shfl_xor_sync(0xffffffff, sum1, 1);
        sum1 += __shfl_xor_sync(0xffffffff, sum1, 2);
        l[0] = l[0] * alpha0 + sum0;
        l[1] = l[1] * alpha1 + sum1;

#pragma unroll
        for (int nt = 0; nt < 16; nt++) {
            Oa[nt][0] *= alpha0; Oa[nt][1] *= alpha0;
            Oa[nt][2] *= alpha1; Oa[nt][3] *= alpha1;
        }

        // ---- P V (2-pass fp16), P split hi/lo in registers ----
        const uint32_t vBase = s0 + lrow * SVB + lkoff;
#pragma unroll
        for (int ks = 0; ks < 4; ks++) {
            uint32_t ph[4], pl[4];
#pragma unroll
            for (int hf = 0; hf < 2; hf++) {
                const int j = 2 * ks + hf;
                __half2 h01 = __floats2half2_rn(Sa[j][0], Sa[j][1]);
                __half2 h23 = __floats2half2_rn(Sa[j][2], Sa[j][3]);
                ph[2*hf]     = *(uint32_t*)&h01;
                ph[2*hf + 1] = *(uint32_t*)&h23;
                __half2 l01 = __floats2half2_rn(Sa[j][0] - __half2float(h01.x),
                                                Sa[j][1] - __half2float(h01.y));
                __half2 l23 = __floats2half2_rn(Sa[j][2] - __half2float(h23.x),
                                                Sa[j][3] - __half2float(h23.y));
                pl[2*hf]     = *(uint32_t*)&l01;
                pl[2*hf + 1] = *(uint32_t*)&l23;
            }
#pragma unroll
            for (int nb = 0; nb < 8; nb++) {
                uint32_t vb[4];
                ldsm4(vb, vBase + AVT + nb * 16 * SVB + ks * 32);
                mma_f16(Oa[2*nb],   ph, vb[0], vb[2]);
                mma_f16(Oa[2*nb+1], ph, vb[1], vb[3]);
                mma_f16(Oa[2*nb],   pl, vb[0], vb[2]);
                mma_f16(Oa[2*nb+1], pl, vb[1], vb[3]);
            }
        }
    }

    // ---- epilogue: normalize, write fp16 hi plane ----
    const float invl0 = 1.f / l[0];
    const float invl1 = 1.f / l[1];
    const int r0g = q0 + w * 16 + grp;
    const size_t row0 = (size_t)(b * SEQ + r0g) * DIM + h * HD;
    const size_t row1 = row0 + (size_t)8 * DIM;
#pragma unroll
    for (int nt = 0; nt < 16; nt++) {
        const int col = nt * 8 + tig * 2;
        float o0 = Oa[nt][0] * invl0, o1 = Oa[nt][1] * invl0;
        float o2 = Oa[nt][2] * invl1, o3 = Oa[nt][3] * invl1;
        *(__half2*)(Ohi + row0 + col) = __floats2half2_rn(o0, o1);
        *(__half2*)(Ohi + row1 + col) = __floats2half2_rn(o2, o3);
    }
}

// ---------------------------------------------------------------------------
extern "C" void kernel_launch(void* const* d_in, const int* in_sizes, int n_in,
                              void* d_out, int out_size)
{
    (void)in_sizes; (void)n_in; (void)out_size;
    const float* x  = (const float*)d_in[0];
    const float* Wq = (const float*)d_in[1];
    const float* Wk = (const float*)d_in[2];
    const float* Wv = (const float*)d_in[3];
    const float* Wo = (const float*)d_in[4];
    const float* bo = (const float*)d_in[5];
    float* out = (float*)d_out;

    float *q, *k;
    __half *xh, *xl, *ah, *w16, *qh, *ql, *kh, *vh;
    cudaGetSymbolAddress((void**)&q,   g_q);
    cudaGetSymbolAddress((void**)&k,   g_k);
    cudaGetSymbolAddress((void**)&xh,  g_xh);
    cudaGetSymbolAddress((void**)&xl,  g_xl);
    cudaGetSymbolAddress((void**)&ah,  g_ah);
    cudaGetSymbolAddress((void**)&w16, g_w16);
    cudaGetSymbolAddress((void**)&qh,  g_qh);
    cudaGetSymbolAddress((void**)&ql,  g_ql);
    cudaGetSymbolAddress((void**)&kh,  g_kh);
    cudaGetSymbolAddress((void**)&vh,  g_vh);

    const size_t WSZ = (size_t)DIM * DIM;
    const int nx4 = (MROWS * DIM) / 4;
    const int nw4 = (DIM * DIM) / 4;

    split16_kernel<<<nx4 / 256, 256>>>(x, xh, xl, nx4);
    cvt16_kernel<<<nw4 / 256, 256>>>(Wq, w16 + 0 * WSZ, nw4);
    cvt16_kernel<<<nw4 / 256, 256>>>(Wk, w16 + 1 * WSZ, nw4);
    cvt16_kernel<<<nw4 / 256, 256>>>(Wv, w16 + 2 * WSZ, nw4);
    cvt16_kernel<<<nw4 / 256, 256>>>(Wo, w16 + 3 * WSZ, nw4);

    cudaFuncSetAttribute(gemm_mma_kernel<true, false>,
                         cudaFuncAttributeMaxDynamicSharedMemorySize, GSMEM);
    cudaFuncSetAttribute(gemm_mma_kernel<false, true>,
                         cudaFuncAttributeMaxDynamicSharedMemorySize, GSMEM);
    cudaFuncSetAttribute(gemm_mma_kernel<false, false>,
                         cudaFuncAttributeMaxDynamicSharedMemorySize, GSMEM);

    dim3 ggrid(DIM / 128, MROWS / 128);
    // Q, K: 2-pass, fp32 out (for RoPE)
    gemm_mma_kernel<true, false><<<ggrid, 256, GSMEM>>>(
        xh, xl, w16 + 0 * WSZ, nullptr, q, nullptr, MROWS, DIM, DIM);
    gemm_mma_kernel<true, false><<<ggrid, 256, GSMEM>>>(
        xh, xl, w16 + 1 * WSZ, nullptr, k, nullptr, MROWS, DIM, DIM);
    // V: 1-pass, fp16 out direct to vh
    gemm_mma_kernel<false, true><<<ggrid, 256, GSMEM>>>(
        xh, nullptr, w16 + 2 * WSZ, nullptr, nullptr, vh, MROWS, DIM, DIM);

    int rope_threads = BATCH * SEQ * NHEAD * 64;
    rope_split16_kernel<<<rope_threads / 256, 256>>>(q, qh, ql);
    rope_cvt16_kernel<<<rope_threads / 256, 256>>>(k, kh);

    cudaFuncSetAttribute(attn_mma_kernel,
                         cudaFuncAttributeMaxDynamicSharedMemorySize, ASMEM);
    attn_mma_kernel<<<dim3(SEQ / 128, BATCH * NHEAD), 256, ASMEM>>>(
        qh, ql, kh, vh, ah);

    // Output projection: 1-pass, fp32 out with bias
    gemm_mma_kernel<false, false><<<ggrid, 256, GSMEM>>>(
        ah, nullptr, w16 + 3 * WSZ, bo, out, nullptr, MROWS, DIM, DIM);
}

// round 12
// speedup vs baseline: 1.6369x; 1.2481x over previous
#include <cuda_runtime.h>
#include <cuda_fp16.h>
#include <math.h>
#include <stdint.h>

#define BATCH 4
#define SEQ   2048
#define DIM   2048
#define NHEAD 16
#define HD    128
#define MROWS (BATCH*SEQ)   // 8192

// ---------------- scratch (static device globals) ----------------
__device__ float g_q[(size_t)MROWS * DIM];
__device__ float g_k[(size_t)MROWS * DIM];
__device__ __half g_xh[(size_t)MROWS * DIM];
__device__ __half g_ah[(size_t)MROWS * DIM];
__device__ __half g_w16[4][(size_t)DIM * DIM];
__device__ __half g_qh[(size_t)MROWS * DIM];
__device__ __half g_ql[(size_t)MROWS * DIM];
__device__ __half g_kh[(size_t)MROWS * DIM];
__device__ __half g_vh[(size_t)MROWS * DIM];

// ---------------- low-level helpers ----------------
__device__ __forceinline__ uint32_t smem_u32(const void* p) {
    uint32_t a;
    asm("{ .reg .u64 t; cvta.to.shared.u64 t, %1; cvt.u32.u64 %0, t; }" : "=r"(a) : "l"(p));
    return a;
}
__device__ __forceinline__ void cp_async16(uint32_t s, const void* g) {
    asm volatile("cp.async.cg.shared.global [%0], [%1], 16;" :: "r"(s), "l"(g));
}
#define CP_COMMIT()  asm volatile("cp.async.commit_group;" ::: "memory")
#define CP_WAIT(n)   asm volatile("cp.async.wait_group %0;" :: "n"(n) : "memory")

__device__ __forceinline__ void ldsm4(uint32_t* r, uint32_t addr) {
    asm volatile("ldmatrix.sync.aligned.m8n8.x4.shared.b16 {%0,%1,%2,%3}, [%4];"
                 : "=r"(r[0]), "=r"(r[1]), "=r"(r[2]), "=r"(r[3]) : "r"(addr));
}
__device__ __forceinline__ void mma_f16(float* d, const uint32_t* a, uint32_t b0, uint32_t b1) {
    asm volatile(
        "mma.sync.aligned.m16n8k16.row.col.f32.f16.f16.f32 "
        "{%0,%1,%2,%3}, {%4,%5,%6,%7}, {%8,%9}, {%0,%1,%2,%3};"
        : "+f"(d[0]), "+f"(d[1]), "+f"(d[2]), "+f"(d[3])
        : "r"(a[0]), "r"(a[1]), "r"(a[2]), "r"(a[3]), "r"(b0), "r"(b1));
}

// ---------------------------------------------------------------------------
// fp32 -> fp16 round only
// ---------------------------------------------------------------------------
__global__ __launch_bounds__(256)
void cvt16_kernel(const float* __restrict__ src, __half* __restrict__ dst, int n4)
{
    int i = blockIdx.x * blockDim.x + threadIdx.x;
    if (i >= n4) return;
    float4 x = ((const float4*)src)[i];
    __half2 H0; H0.x = __float2half(x.x); H0.y = __float2half(x.y);
    __half2 H1; H1.x = __float2half(x.z); H1.y = __float2half(x.w);
    ((__half2*)dst)[i*2]   = H0;
    ((__half2*)dst)[i*2+1] = H1;
}

// ---------------------------------------------------------------------------
// Fused RoPE + fp16 split (Q path) — keeps fp32-accumulator precision for attention
// ---------------------------------------------------------------------------
__global__ __launch_bounds__(256)
void rope_split16_kernel(const float* __restrict__ src,
                         __half* __restrict__ hi, __half* __restrict__ lo)
{
    int idx = blockIdx.x * blockDim.x + threadIdx.x;
    int i = idx & 63;
    int h = (idx >> 6) & (NHEAD - 1);
    int s = (idx >> 10) & (SEQ - 1);
    int b = idx >> 21;

    float inv = expf(-9.210340371976184f * ((float)i * (1.0f / 64.0f)));
    float ang = (float)s * inv;
    float c, sn;
    sincosf(ang, &sn, &c);

    size_t base = (size_t)(b * SEQ + s) * DIM + h * HD;
    float t1 = src[base + i];
    float t2 = src[base + i + 64];
    float o1 = t1 * c - t2 * sn;
    float o2 = t2 * c + t1 * sn;

    __half h1 = __float2half(o1);
    __half h2 = __float2half(o2);
    hi[base + i]      = h1;
    hi[base + i + 64] = h2;
    lo[base + i]      = __float2half(o1 - __half2float(h1));
    lo[base + i + 64] = __float2half(o2 - __half2float(h2));
}

// Fused RoPE + fp16 round (K path, single plane)
__global__ __launch_bounds__(256)
void rope_cvt16_kernel(const float* __restrict__ src, __half* __restrict__ dst)
{
    int idx = blockIdx.x * blockDim.x + threadIdx.x;
    int i = idx & 63;
    int h = (idx >> 6) & (NHEAD - 1);
    int s = (idx >> 10) & (SEQ - 1);
    int b = idx >> 21;

    float inv = expf(-9.210340371976184f * ((float)i * (1.0f / 64.0f)));
    float ang = (float)s * inv;
    float c, sn;
    sincosf(ang, &sn, &c);

    size_t base = (size_t)(b * SEQ + s) * DIM + h * HD;
    float t1 = src[base + i];
    float t2 = src[base + i + 64];
    dst[base + i]      = __float2half(t1 * c - t2 * sn);
    dst[base + i + 64] = __float2half(t2 * c + t1 * sn);
}

// ---------------------------------------------------------------------------
// fp16 GEMM via mma.sync. TWOPASS: A split hi/lo. HALFOUT: fp16 output.
// CTA tile 128x128, BK=32, 8 warps, 3-stage cp.async pipeline, 2 CTA/SM.
// ---------------------------------------------------------------------------
#define GBK       32
#define ROW_B     80
#define PLANE_B   (128 * ROW_B)        // 10240
#define STAGE_B   (3 * PLANE_B)        // 30720
#define NSTAGE    3
#define GSMEM     (NSTAGE * STAGE_B)   // 92160

template<bool TWOPASS>
__device__ __forceinline__ void load_stage(uint32_t st_u32,
    const __half* __restrict__ Ah, const __half* __restrict__ Al,
    const __half* __restrict__ Bh,
    int m0, int n0, int K, int kc, int tid)
{
#pragma unroll
    for (int p = 0; p < 3; p++) {
        if (!TWOPASS && p == 1) continue;
        const __half* src = (p == 0) ? Ah : (p == 1) ? Al : Bh;
        const int rbase = (p < 2) ? m0 : n0;
#pragma unroll
        for (int i = 0; i < 2; i++) {
            int idx = i * 256 + tid;
            int r = idx >> 2, c = idx & 3;
            const void* g = src + (size_t)(rbase + r) * K + kc + c * 8;
            cp_async16(st_u32 + p * PLANE_B + r * ROW_B + c * 16, g);
        }
    }
}

template<bool TWOPASS, bool HALFOUT>
__global__ __launch_bounds__(256, 2)
void gemm_mma_kernel(const __half* __restrict__ Ah, const __half* __restrict__ Al,
                     const __half* __restrict__ Bh,
                     const float* __restrict__ bias, float* __restrict__ C,
                     __half* __restrict__ C16,
                     int M, int N, int K)
{
    extern __shared__ char smem[];
    const uint32_t sm0 = smem_u32(smem);
    const int tid  = threadIdx.x;
    const int wid  = tid >> 5;
    const int lane = tid & 31;
    const int wm   = wid & 3;
    const int wn   = wid >> 2;
    const int m0 = blockIdx.y * 128;
    const int n0 = blockIdx.x * 128;
    const int nchunk = K / GBK;

    float acc[2][8][4];
#pragma unroll
    for (int mt = 0; mt < 2; mt++)
#pragma unroll
        for (int nt = 0; nt < 8; nt++)
#pragma unroll
            for (int q = 0; q < 4; q++) acc[mt][nt][q] = 0.f;

    const int lrow  = lane & 15;
    const int lkoff = (lane >> 4) * 16;

    load_stage<TWOPASS>(sm0,           Ah, Al, Bh, m0, n0, K, 0,   tid);
    CP_COMMIT();
    load_stage<TWOPASS>(sm0 + STAGE_B, Ah, Al, Bh, m0, n0, K, GBK, tid);
    CP_COMMIT();

    for (int i = 0; i < nchunk; i++) {
        CP_WAIT(1);
        __syncthreads();

        if (i + 2 < nchunk)
            load_stage<TWOPASS>(sm0 + ((i + 2) % NSTAGE) * STAGE_B,
                                Ah, Al, Bh, m0, n0, K, (i + 2) * GBK, tid);
        CP_COMMIT();

        const uint32_t st = sm0 + (i % NSTAGE) * STAGE_B;
        const uint32_t aRow = st + (wm * 32 + lrow) * ROW_B + lkoff;
        const uint32_t bRow = st + 2 * PLANE_B + (wn * 64 + lrow) * ROW_B + lkoff;

#pragma unroll
        for (int ks = 0; ks < 2; ks++) {
            uint32_t ah[2][4], al[2][4], bh[4][4];
#pragma unroll
            for (int mt = 0; mt < 2; mt++) {
                ldsm4(ah[mt], aRow + mt * (16 * ROW_B) + ks * 32);
                if (TWOPASS)
                    ldsm4(al[mt], aRow + PLANE_B + mt * (16 * ROW_B) + ks * 32);
            }
#pragma unroll
            for (int np = 0; np < 4; np++)
                ldsm4(bh[np], bRow + np * (16 * ROW_B) + ks * 32);
#pragma unroll
            for (int mt = 0; mt < 2; mt++)
#pragma unroll
                for (int nt = 0; nt < 8; nt++) {
                    const int np = nt >> 1, h = nt & 1;
                    mma_f16(acc[mt][nt], ah[mt], bh[np][h], bh[np][2 + h]);
                    if (TWOPASS)
                        mma_f16(acc[mt][nt], al[mt], bh[np][h], bh[np][2 + h]);
                }
        }
        __syncthreads();
    }

    const int grp = lane >> 2;
    const int tig = lane & 3;
#pragma unroll
    for (int mt = 0; mt < 2; mt++) {
        const int rbase = m0 + wm * 32 + mt * 16 + grp;
#pragma unroll
        for (int nt = 0; nt < 8; nt++) {
            const int col = n0 + wn * 64 + nt * 8 + tig * 2;
            float bx = 0.f, by = 0.f;
            if (bias) { bx = bias[col]; by = bias[col + 1]; }
            float v00 = acc[mt][nt][0] + bx, v01 = acc[mt][nt][1] + by;
            float v10 = acc[mt][nt][2] + bx, v11 = acc[mt][nt][3] + by;
            if (HALFOUT) {
                *(__half2*)(C16 + (size_t)rbase * N + col)       = __floats2half2_rn(v00, v01);
                *(__half2*)(C16 + (size_t)(rbase + 8) * N + col) = __floats2half2_rn(v10, v11);
            } else {
                float2 v0; v0.x = v00; v0.y = v01;
                float2 v1; v1.x = v10; v1.y = v11;
                *(float2*)(C + (size_t)rbase * N + col)       = v0;
                *(float2*)(C + (size_t)(rbase + 8) * N + col) = v1;
            }
        }
    }
}

// ---------------------------------------------------------------------------
// Causal flash attention, fp16 2-pass (verified R7/R10). Writes hi plane only.
// ---------------------------------------------------------------------------
#define SKB 272
#define SVB 144
#define AQH 0
#define AQL (AQH + 128*SKB)
#define AKH (AQL + 128*SKB)
#define AVT (AKH + 64*SKB)
#define ASMEM (AVT + 128*SVB)   // 105472

__global__ __launch_bounds__(256, 1)
void attn_mma_kernel(const __half* __restrict__ Qh, const __half* __restrict__ Ql,
                     const __half* __restrict__ Kh, const __half* __restrict__ Vh,
                     __half* __restrict__ Ohi)
{
    extern __shared__ char smem[];
    const uint32_t s0 = smem_u32(smem);
    const int tid  = threadIdx.x;
    const int w    = tid >> 5;
    const int lane = tid & 31;
    const int grp  = lane >> 2;
    const int tig  = lane & 3;
    const int lrow  = lane & 15;
    const int lkoff = (lane >> 4) * 16;

    const int bh = blockIdx.y;
    const int b  = bh >> 4;
    const int h  = bh & (NHEAD - 1);
    const int qt = blockIdx.x;
    const int q0 = qt * 128;

    const size_t rowQ = (size_t)(b * SEQ + q0);
    const __half* qh_g = Qh + rowQ * DIM + h * HD;
    const __half* ql_g = Ql + rowQ * DIM + h * HD;

#pragma unroll
    for (int u = 0; u < 8; u++) {
        int idx = u * 256 + tid;
        int r = idx >> 4, c = idx & 15;
        cp_async16(s0 + AQH + r * SKB + c * 16, qh_g + (size_t)r * DIM + c * 8);
        cp_async16(s0 + AQL + r * SKB + c * 16, ql_g + (size_t)r * DIM + c * 8);
    }
    CP_COMMIT();

    float m[2] = {-1e30f, -1e30f};
    float l[2] = {0.f, 0.f};
    float Oa[16][4];
#pragma unroll
    for (int nt = 0; nt < 16; nt++)
#pragma unroll
        for (int q = 0; q < 4; q++) Oa[nt][q] = 0.f;

    const float scale = 0.08838834764831845f;
    const int nkt = 2 * qt + 2;

    for (int kt = 0; kt < nkt; kt++) {
        const int kv0 = kt * 64;
        const size_t rowK = (size_t)(b * SEQ + kv0);
        const __half* kh_g = Kh + rowK * DIM + h * HD;
        const __half* vh_g = Vh + rowK * DIM + h * HD;

        __syncthreads();

#pragma unroll
        for (int u = 0; u < 4; u++) {
            int idx = u * 256 + tid;
            int r = idx >> 4, c = idx & 15;
            cp_async16(s0 + AKH + r * SKB + c * 16, kh_g + (size_t)r * DIM + c * 8);
        }
        CP_COMMIT();

#pragma unroll
        for (int u = 0; u < 4; u++) {
            int idx = u * 256 + tid;
            int kv = idx & 63, c = idx >> 6;
            uint4 xh = *(const uint4*)(vh_g + (size_t)kv * DIM + c * 8);
            const uint16_t* uh = (const uint16_t*)&xh;
#pragma unroll
            for (int j = 0; j < 8; j++)
                *(uint16_t*)(smem + AVT + (c * 8 + j) * SVB + kv * 2) = uh[j];
        }
        CP_WAIT(0);
        __syncthreads();

        // ---- S = Q K^T (2-pass fp16) ----
        float Sa[8][4];
#pragma unroll
        for (int j = 0; j < 8; j++)
#pragma unroll
            for (int q = 0; q < 4; q++) Sa[j][q] = 0.f;

        const uint32_t aBase = s0 + (w * 16 + lrow) * SKB + lkoff;
        const uint32_t kBase = s0 + lrow * SKB + lkoff;
#pragma unroll
        for (int ks = 0; ks < 8; ks++) {
            uint32_t ah[4], al[4];
            ldsm4(ah, aBase + AQH + ks * 32);
            ldsm4(al, aBase + AQL + ks * 32);
#pragma unroll
            for (int p = 0; p < 4; p++) {
                uint32_t kb[4];
                ldsm4(kb, kBase + AKH + p * 16 * SKB + ks * 32);
                mma_f16(Sa[2*p],   ah, kb[0], kb[2]);
                mma_f16(Sa[2*p+1], ah, kb[1], kb[3]);
                mma_f16(Sa[2*p],   al, kb[0], kb[2]);
                mma_f16(Sa[2*p+1], al, kb[1], kb[3]);
            }
        }

        // ---- scale + causal mask ----
        const int r0g = q0 + w * 16 + grp;
        const int r1g = r0g + 8;
        const bool need_mask = (kt >= 2 * qt);
#pragma unroll
        for (int j = 0; j < 8; j++) {
            const int c0 = kv0 + j * 8 + tig * 2;
            Sa[j][0] *= scale; Sa[j][1] *= scale;
            Sa[j][2] *= scale; Sa[j][3] *= scale;
            if (need_mask) {
                if (c0     > r0g) Sa[j][0] = -1e9f;
                if (c0 + 1 > r0g) Sa[j][1] = -1e9f;
                if (c0     > r1g) Sa[j][2] = -1e9f;
                if (c0 + 1 > r1g) Sa[j][3] = -1e9f;
            }
        }

        // ---- online softmax ----
        float mx0 = -1e30f, mx1 = -1e30f;
#pragma unroll
        for (int j = 0; j < 8; j++) {
            mx0 = fmaxf(mx0, fmaxf(Sa[j][0], Sa[j][1]));
            mx1 = fmaxf(mx1, fmaxf(Sa[j][2], Sa[j][3]));
        }
        mx0 = fmaxf(mx0, __shfl_xor_sync(0xffffffff, mx0, 1));
        mx0 = fmaxf(mx0, __shfl_xor_sync(0xffffffff, mx0, 2));
        mx1 = fmaxf(mx1, __shfl_xor_sync(0xffffffff, mx1, 1));
        mx1 = fmaxf(mx1, __shfl_xor_sync(0xffffffff, mx1, 2));

        const float mn0 = fmaxf(m[0], mx0);
        const float mn1 = fmaxf(m[1], mx1);
        const float alpha0 = __expf(m[0] - mn0);
        const float alpha1 = __expf(m[1] - mn1);
        m[0] = mn0; m[1] = mn1;

        float sum0 = 0.f, sum1 = 0.f;
#pragma unroll
        for (int j = 0; j < 8; j++) {
            Sa[j][0] = __expf(Sa[j][0] - mn0);
            Sa[j][1] = __expf(Sa[j][1] - mn0);
            Sa[j][2] = __expf(Sa[j][2] - mn1);
            Sa[j][3] = __expf(Sa[j][3] - mn1);
            sum0 += Sa[j][0] + Sa[j][1];
            sum1 += Sa[j][2] + Sa[j][3];
        }
        sum0 += __shfl_xor_sync(0xffffffff, sum0, 1);
        sum0 += __shfl_xor_sync(0xffffffff, sum0, 2);
        sum1 += __shfl_xor_sync(0xffffffff, sum1, 1);
        sum1 += __shfl_xor_sync(0xffffffff, sum1, 2);
        l[0] = l[0] * alpha0 + sum0;
        l[1] = l[1] * alpha1 + sum1;

#pragma unroll
        for (int nt = 0; nt < 16; nt++) {
            Oa[nt][0] *= alpha0; Oa[nt][1] *= alpha0;
            Oa[nt][2] *= alpha1; Oa[nt][3] *= alpha1;
        }

        // ---- P V (2-pass fp16), P split hi/lo in registers ----
        const uint32_t vBase = s0 + lrow * SVB + lkoff;
#pragma unroll
        for (int ks = 0; ks < 4; ks++) {
            uint32_t ph[4], pl[4];
#pragma unroll
            for (int hf = 0; hf < 2; hf++) {
                const int j = 2 * ks + hf;
                __half2 h01 = __floats2half2_rn(Sa[j][0], Sa[j][1]);
                __half2 h23 = __floats2half2_rn(Sa[j][2], Sa[j][3]);
                ph[2*hf]     = *(uint32_t*)&h01;
                ph[2*hf + 1] = *(uint32_t*)&h23;
                __half2 l01 = __floats2half2_rn(Sa[j][0] - __half2float(h01.x),
                                                Sa[j][1] - __half2float(h01.y));
                __half2 l23 = __floats2half2_rn(Sa[j][2] - __half2float(h23.x),
                                                Sa[j][3] - __half2float(h23.y));
                pl[2*hf]     = *(uint32_t*)&l01;
                pl[2*hf + 1] = *(uint32_t*)&l23;
            }
#pragma unroll
            for (int nb = 0; nb < 8; nb++) {
                uint32_t vb[4];
                ldsm4(vb, vBase + AVT + nb * 16 * SVB + ks * 32);
                mma_f16(Oa[2*nb],   ph, vb[0], vb[2]);
                mma_f16(Oa[2*nb+1], ph, vb[1], vb[3]);
                mma_f16(Oa[2*nb],   pl, vb[0], vb[2]);
                mma_f16(Oa[2*nb+1], pl, vb[1], vb[3]);
            }
        }
    }

    // ---- epilogue: normalize, write fp16 hi plane ----
    const float invl0 = 1.f / l[0];
    const float invl1 = 1.f / l[1];
    const int r0g = q0 + w * 16 + grp;
    const size_t row0 = (size_t)(b * SEQ + r0g) * DIM + h * HD;
    const size_t row1 = row0 + (size_t)8 * DIM;
#pragma unroll
    for (int nt = 0; nt < 16; nt++) {
        const int col = nt * 8 + tig * 2;
        float o0 = Oa[nt][0] * invl0, o1 = Oa[nt][1] * invl0;
        float o2 = Oa[nt][2] * invl1, o3 = Oa[nt][3] * invl1;
        *(__half2*)(Ohi + row0 + col) = __floats2half2_rn(o0, o1);
        *(__half2*)(Ohi + row1 + col) = __floats2half2_rn(o2, o3);
    }
}

// ---------------------------------------------------------------------------
extern "C" void kernel_launch(void* const* d_in, const int* in_sizes, int n_in,
                              void* d_out, int out_size)
{
    (void)in_sizes; (void)n_in; (void)out_size;
    const float* x  = (const float*)d_in[0];
    const float* Wq = (const float*)d_in[1];
    const float* Wk = (const float*)d_in[2];
    const float* Wv = (const float*)d_in[3];
    const float* Wo = (const float*)d_in[4];
    const float* bo = (const float*)d_in[5];
    float* out = (float*)d_out;

    float *q, *k;
    __half *xh, *ah, *w16, *qh, *ql, *kh, *vh;
    cudaGetSymbolAddress((void**)&q,   g_q);
    cudaGetSymbolAddress((void**)&k,   g_k);
    cudaGetSymbolAddress((void**)&xh,  g_xh);
    cudaGetSymbolAddress((void**)&ah,  g_ah);
    cudaGetSymbolAddress((void**)&w16, g_w16);
    cudaGetSymbolAddress((void**)&qh,  g_qh);
    cudaGetSymbolAddress((void**)&ql,  g_ql);
    cudaGetSymbolAddress((void**)&kh,  g_kh);
    cudaGetSymbolAddress((void**)&vh,  g_vh);

    const size_t WSZ = (size_t)DIM * DIM;
    const int nx4 = (MROWS * DIM) / 4;
    const int nw4 = (DIM * DIM) / 4;

    cvt16_kernel<<<nx4 / 256, 256>>>(x, xh, nx4);
    cvt16_kernel<<<nw4 / 256, 256>>>(Wq, w16 + 0 * WSZ, nw4);
    cvt16_kernel<<<nw4 / 256, 256>>>(Wk, w16 + 1 * WSZ, nw4);
    cvt16_kernel<<<nw4 / 256, 256>>>(Wv, w16 + 2 * WSZ, nw4);
    cvt16_kernel<<<nw4 / 256, 256>>>(Wo, w16 + 3 * WSZ, nw4);

    cudaFuncSetAttribute(gemm_mma_kernel<false, true>,
                         cudaFuncAttributeMaxDynamicSharedMemorySize, GSMEM);
    cudaFuncSetAttribute(gemm_mma_kernel<false, false>,
                         cudaFuncAttributeMaxDynamicSharedMemorySize, GSMEM);

    dim3 ggrid(DIM / 128, MROWS / 128);
    // Q, K: 1-pass, fp32 out (for RoPE; fp32 accumulator preserved into hi/lo split)
    gemm_mma_kernel<false, false><<<ggrid, 256, GSMEM>>>(
        xh, nullptr, w16 + 0 * WSZ, nullptr, q, nullptr, MROWS, DIM, DIM);
    gemm_mma_kernel<false, false><<<ggrid, 256, GSMEM>>>(
        xh, nullptr, w16 + 1 * WSZ, nullptr, k, nullptr, MROWS, DIM, DIM);
    // V: 1-pass, fp16 out direct to vh
    gemm_mma_kernel<false, true><<<ggrid, 256, GSMEM>>>(
        xh, nullptr, w16 + 2 * WSZ, nullptr, nullptr, vh, MROWS, DIM, DIM);

    int rope_threads = BATCH * SEQ * NHEAD * 64;
    rope_split16_kernel<<<rope_threads / 256, 256>>>(q, qh, ql);
    rope_cvt16_kernel<<<rope_threads / 256, 256>>>(k, kh);

    cudaFuncSetAttribute(attn_mma_kernel,
                         cudaFuncAttributeMaxDynamicSharedMemorySize, ASMEM);
    attn_mma_kernel<<<dim3(SEQ / 128, BATCH * NHEAD), 256, ASMEM>>>(
        qh, ql, kh, vh, ah);

    // Output projection: 1-pass, fp32 out with bias
    gemm_mma_kernel<false, false><<<ggrid, 256, GSMEM>>>(
        ah, nullptr, w16 + 3 * WSZ, bo, out, nullptr, MROWS, DIM, DIM);
}

// round 13
// speedup vs baseline: 1.7948x; 1.0964x over previous
#include <cuda_runtime.h>
#include <cuda_fp16.h>
#include <math.h>
#include <stdint.h>

#define BATCH 4
#define SEQ   2048
#define DIM   2048
#define NHEAD 16
#define HD    128
#define MROWS (BATCH*SEQ)   // 8192

// ---------------- scratch (static device globals) ----------------
__device__ float g_q[(size_t)MROWS * DIM];
__device__ float g_k[(size_t)MROWS * DIM];
__device__ __half g_xh[(size_t)MROWS * DIM];
__device__ __half g_ah[(size_t)MROWS * DIM];
__device__ __half g_w16[4][(size_t)DIM * DIM];
__device__ __half g_qh[(size_t)MROWS * DIM];
__device__ __half g_kh[(size_t)MROWS * DIM];
__device__ __half g_vh[(size_t)MROWS * DIM];

// ---------------- low-level helpers ----------------
__device__ __forceinline__ uint32_t smem_u32(const void* p) {
    uint32_t a;
    asm("{ .reg .u64 t; cvta.to.shared.u64 t, %1; cvt.u32.u64 %0, t; }" : "=r"(a) : "l"(p));
    return a;
}
__device__ __forceinline__ void cp_async16(uint32_t s, const void* g) {
    asm volatile("cp.async.cg.shared.global [%0], [%1], 16;" :: "r"(s), "l"(g));
}
#define CP_COMMIT()  asm volatile("cp.async.commit_group;" ::: "memory")
#define CP_WAIT(n)   asm volatile("cp.async.wait_group %0;" :: "n"(n) : "memory")

__device__ __forceinline__ void ldsm4(uint32_t* r, uint32_t addr) {
    asm volatile("ldmatrix.sync.aligned.m8n8.x4.shared.b16 {%0,%1,%2,%3}, [%4];"
                 : "=r"(r[0]), "=r"(r[1]), "=r"(r[2]), "=r"(r[3]) : "r"(addr));
}
__device__ __forceinline__ void mma_f16(float* d, const uint32_t* a, uint32_t b0, uint32_t b1) {
    asm volatile(
        "mma.sync.aligned.m16n8k16.row.col.f32.f16.f16.f32 "
        "{%0,%1,%2,%3}, {%4,%5,%6,%7}, {%8,%9}, {%0,%1,%2,%3};"
        : "+f"(d[0]), "+f"(d[1]), "+f"(d[2]), "+f"(d[3])
        : "r"(a[0]), "r"(a[1]), "r"(a[2]), "r"(a[3]), "r"(b0), "r"(b1));
}

// ---------------------------------------------------------------------------
// fp32 -> fp16 round only
// ---------------------------------------------------------------------------
__global__ __launch_bounds__(256)
void cvt16_kernel(const float* __restrict__ src, __half* __restrict__ dst, int n4)
{
    int i = blockIdx.x * blockDim.x + threadIdx.x;
    if (i >= n4) return;
    float4 x = ((const float4*)src)[i];
    __half2 H0; H0.x = __float2half(x.x); H0.y = __float2half(x.y);
    __half2 H1; H1.x = __float2half(x.z); H1.y = __float2half(x.w);
    ((__half2*)dst)[i*2]   = H0;
    ((__half2*)dst)[i*2+1] = H1;
}

// ---------------------------------------------------------------------------
// Fused RoPE + fp16 round (Q and K paths, single plane)
// ---------------------------------------------------------------------------
__global__ __launch_bounds__(256)
void rope_cvt16_kernel(const float* __restrict__ src, __half* __restrict__ dst)
{
    int idx = blockIdx.x * blockDim.x + threadIdx.x;
    int i = idx & 63;
    int h = (idx >> 6) & (NHEAD - 1);
    int s = (idx >> 10) & (SEQ - 1);
    int b = idx >> 21;

    float inv = expf(-9.210340371976184f * ((float)i * (1.0f / 64.0f)));
    float ang = (float)s * inv;
    float c, sn;
    sincosf(ang, &sn, &c);

    size_t base = (size_t)(b * SEQ + s) * DIM + h * HD;
    float t1 = src[base + i];
    float t2 = src[base + i + 64];
    dst[base + i]      = __float2half(t1 * c - t2 * sn);
    dst[base + i + 64] = __float2half(t2 * c + t1 * sn);
}

// ---------------------------------------------------------------------------
// fp16 1-pass GEMM via mma.sync. HALFOUT: fp16 output.
// CTA tile 128x128, BK=32, 8 warps, 3-stage cp.async pipeline, 2 CTA/SM.
// ---------------------------------------------------------------------------
#define GBK       32
#define ROW_B     80
#define PLANE_B   (128 * ROW_B)        // 10240
#define STAGE_B   (3 * PLANE_B)        // 30720 (Ah, [unused], Bh)
#define NSTAGE    3
#define GSMEM     (NSTAGE * STAGE_B)   // 92160

__device__ __forceinline__ void load_stage(uint32_t st_u32,
    const __half* __restrict__ Ah, const __half* __restrict__ Bh,
    int m0, int n0, int K, int kc, int tid)
{
#pragma unroll
    for (int p = 0; p < 3; p++) {
        if (p == 1) continue;
        const __half* src = (p == 0) ? Ah : Bh;
        const int rbase = (p == 0) ? m0 : n0;
#pragma unroll
        for (int i = 0; i < 2; i++) {
            int idx = i * 256 + tid;
            int r = idx >> 2, c = idx & 3;
            const void* g = src + (size_t)(rbase + r) * K + kc + c * 8;
            cp_async16(st_u32 + p * PLANE_B + r * ROW_B + c * 16, g);
        }
    }
}

template<bool HALFOUT>
__global__ __launch_bounds__(256, 2)
void gemm_mma_kernel(const __half* __restrict__ Ah, const __half* __restrict__ Bh,
                     const float* __restrict__ bias, float* __restrict__ C,
                     __half* __restrict__ C16,
                     int M, int N, int K)
{
    extern __shared__ char smem[];
    const uint32_t sm0 = smem_u32(smem);
    const int tid  = threadIdx.x;
    const int wid  = tid >> 5;
    const int lane = tid & 31;
    const int wm   = wid & 3;
    const int wn   = wid >> 2;
    const int m0 = blockIdx.y * 128;
    const int n0 = blockIdx.x * 128;
    const int nchunk = K / GBK;

    float acc[2][8][4];
#pragma unroll
    for (int mt = 0; mt < 2; mt++)
#pragma unroll
        for (int nt = 0; nt < 8; nt++)
#pragma unroll
            for (int q = 0; q < 4; q++) acc[mt][nt][q] = 0.f;

    const int lrow  = lane & 15;
    const int lkoff = (lane >> 4) * 16;

    load_stage(sm0,           Ah, Bh, m0, n0, K, 0,   tid);
    CP_COMMIT();
    load_stage(sm0 + STAGE_B, Ah, Bh, m0, n0, K, GBK, tid);
    CP_COMMIT();

    for (int i = 0; i < nchunk; i++) {
        CP_WAIT(1);
        __syncthreads();

        if (i + 2 < nchunk)
            load_stage(sm0 + ((i + 2) % NSTAGE) * STAGE_B,
                       Ah, Bh, m0, n0, K, (i + 2) * GBK, tid);
        CP_COMMIT();

        const uint32_t st = sm0 + (i % NSTAGE) * STAGE_B;
        const uint32_t aRow = st + (wm * 32 + lrow) * ROW_B + lkoff;
        const uint32_t bRow = st + 2 * PLANE_B + (wn * 64 + lrow) * ROW_B + lkoff;

#pragma unroll
        for (int ks = 0; ks < 2; ks++) {
            uint32_t ah[2][4], bh[4][4];
#pragma unroll
            for (int mt = 0; mt < 2; mt++)
                ldsm4(ah[mt], aRow + mt * (16 * ROW_B) + ks * 32);
#pragma unroll
            for (int np = 0; np < 4; np++)
                ldsm4(bh[np], bRow + np * (16 * ROW_B) + ks * 32);
#pragma unroll
            for (int mt = 0; mt < 2; mt++)
#pragma unroll
                for (int nt = 0; nt < 8; nt++) {
                    const int np = nt >> 1, h = nt & 1;
                    mma_f16(acc[mt][nt], ah[mt], bh[np][h], bh[np][2 + h]);
                }
        }
        __syncthreads();
    }

    const int grp = lane >> 2;
    const int tig = lane & 3;
#pragma unroll
    for (int mt = 0; mt < 2; mt++) {
        const int rbase = m0 + wm * 32 + mt * 16 + grp;
#pragma unroll
        for (int nt = 0; nt < 8; nt++) {
            const int col = n0 + wn * 64 + nt * 8 + tig * 2;
            float bx = 0.f, by = 0.f;
            if (bias) { bx = bias[col]; by = bias[col + 1]; }
            float v00 = acc[mt][nt][0] + bx, v01 = acc[mt][nt][1] + by;
            float v10 = acc[mt][nt][2] + bx, v11 = acc[mt][nt][3] + by;
            if (HALFOUT) {
                *(__half2*)(C16 + (size_t)rbase * N + col)       = __floats2half2_rn(v00, v01);
                *(__half2*)(C16 + (size_t)(rbase + 8) * N + col) = __floats2half2_rn(v10, v11);
            } else {
                float2 v0; v0.x = v00; v0.y = v01;
                float2 v1; v1.x = v10; v1.y = v11;
                *(float2*)(C + (size_t)rbase * N + col)       = v0;
                *(float2*)(C + (size_t)(rbase + 8) * N + col) = v1;
            }
        }
    }
}

// ---------------------------------------------------------------------------
// Causal flash attention, fully 1-pass fp16 (fp32 accumulate).
// CTA: 128 q x 64 k per iter, 8 warps. Writes fp16 hi plane.
// ---------------------------------------------------------------------------
#define SKB 272            // Q/K smem row bytes (128 fp16 = 256B + 16 pad)
#define SVB 144            // Vt smem row bytes (64 fp16 = 128B + 16 pad)
#define AQH 0
#define AKH (AQH + 128*SKB)
#define AVT (AKH + 64*SKB)
#define ASMEM (AVT + 128*SVB)   // 70656

__global__ __launch_bounds__(256, 1)
void attn_mma_kernel(const __half* __restrict__ Qh, const __half* __restrict__ Kh,
                     const __half* __restrict__ Vh, __half* __restrict__ Ohi)
{
    extern __shared__ char smem[];
    const uint32_t s0 = smem_u32(smem);
    const int tid  = threadIdx.x;
    const int w    = tid >> 5;
    const int lane = tid & 31;
    const int grp  = lane >> 2;
    const int tig  = lane & 3;
    const int lrow  = lane & 15;
    const int lkoff = (lane >> 4) * 16;

    const int bh = blockIdx.y;
    const int b  = bh >> 4;
    const int h  = bh & (NHEAD - 1);
    const int qt = blockIdx.x;
    const int q0 = qt * 128;

    const size_t rowQ = (size_t)(b * SEQ + q0);
    const __half* qh_g = Qh + rowQ * DIM + h * HD;

    // Q tile -> smem (hi plane only)
#pragma unroll
    for (int u = 0; u < 8; u++) {
        int idx = u * 256 + tid;
        int r = idx >> 4, c = idx & 15;
        cp_async16(s0 + AQH + r * SKB + c * 16, qh_g + (size_t)r * DIM + c * 8);
    }
    CP_COMMIT();

    float m[2] = {-1e30f, -1e30f};
    float l[2] = {0.f, 0.f};
    float Oa[16][4];
#pragma unroll
    for (int nt = 0; nt < 16; nt++)
#pragma unroll
        for (int q = 0; q < 4; q++) Oa[nt][q] = 0.f;

    const float scale = 0.08838834764831845f;
    const int nkt = 2 * qt + 2;

    for (int kt = 0; kt < nkt; kt++) {
        const int kv0 = kt * 64;
        const size_t rowK = (size_t)(b * SEQ + kv0);
        const __half* kh_g = Kh + rowK * DIM + h * HD;
        const __half* vh_g = Vh + rowK * DIM + h * HD;

        __syncthreads();

        // K tile
#pragma unroll
        for (int u = 0; u < 4; u++) {
            int idx = u * 256 + tid;
            int r = idx >> 4, c = idx & 15;
            cp_async16(s0 + AKH + r * SKB + c * 16, kh_g + (size_t)r * DIM + c * 8);
        }
        CP_COMMIT();

        // V tile transposed
#pragma unroll
        for (int u = 0; u < 4; u++) {
            int idx = u * 256 + tid;
            int kv = idx & 63, c = idx >> 6;
            uint4 xh = *(const uint4*)(vh_g + (size_t)kv * DIM + c * 8);
            const uint16_t* uh = (const uint16_t*)&xh;
#pragma unroll
            for (int j = 0; j < 8; j++)
                *(uint16_t*)(smem + AVT + (c * 8 + j) * SVB + kv * 2) = uh[j];
        }
        CP_WAIT(0);
        __syncthreads();

        // ---- S = Q K^T (1-pass fp16, fp32 acc) ----
        float Sa[8][4];
#pragma unroll
        for (int j = 0; j < 8; j++)
#pragma unroll
            for (int q = 0; q < 4; q++) Sa[j][q] = 0.f;

        const uint32_t aBase = s0 + AQH + (w * 16 + lrow) * SKB + lkoff;
        const uint32_t kBase = s0 + AKH + lrow * SKB + lkoff;
#pragma unroll
        for (int ks = 0; ks < 8; ks++) {
            uint32_t ah[4];
            ldsm4(ah, aBase + ks * 32);
#pragma unroll
            for (int p = 0; p < 4; p++) {
                uint32_t kb[4];
                ldsm4(kb, kBase + p * 16 * SKB + ks * 32);
                mma_f16(Sa[2*p],   ah, kb[0], kb[2]);
                mma_f16(Sa[2*p+1], ah, kb[1], kb[3]);
            }
        }

        // ---- scale + causal mask ----
        const int r0g = q0 + w * 16 + grp;
        const int r1g = r0g + 8;
        const bool need_mask = (kt >= 2 * qt);
#pragma unroll
        for (int j = 0; j < 8; j++) {
            const int c0 = kv0 + j * 8 + tig * 2;
            Sa[j][0] *= scale; Sa[j][1] *= scale;
            Sa[j][2] *= scale; Sa[j][3] *= scale;
            if (need_mask) {
                if (c0     > r0g) Sa[j][0] = -1e9f;
                if (c0 + 1 > r0g) Sa[j][1] = -1e9f;
                if (c0     > r1g) Sa[j][2] = -1e9f;
                if (c0 + 1 > r1g) Sa[j][3] = -1e9f;
            }
        }

        // ---- online softmax ----
        float mx0 = -1e30f, mx1 = -1e30f;
#pragma unroll
        for (int j = 0; j < 8; j++) {
            mx0 = fmaxf(mx0, fmaxf(Sa[j][0], Sa[j][1]));
            mx1 = fmaxf(mx1, fmaxf(Sa[j][2], Sa[j][3]));
        }
        mx0 = fmaxf(mx0, __shfl_xor_sync(0xffffffff, mx0, 1));
        mx0 = fmaxf(mx0, __shfl_xor_sync(0xffffffff, mx0, 2));
        mx1 = fmaxf(mx1, __shfl_xor_sync(0xffffffff, mx1, 1));
        mx1 = fmaxf(mx1, __shfl_xor_sync(0xffffffff, mx1, 2));

        const float mn0 = fmaxf(m[0], mx0);
        const float mn1 = fmaxf(m[1], mx1);
        const float alpha0 = __expf(m[0] - mn0);
        const float alpha1 = __expf(m[1] - mn1);
        m[0] = mn0; m[1] = mn1;

        float sum0 = 0.f, sum1 = 0.f;
#pragma unroll
        for (int j = 0; j < 8; j++) {
            Sa[j][0] = __expf(Sa[j][0] - mn0);
            Sa[j][1] = __expf(Sa[j][1] - mn0);
            Sa[j][2] = __expf(Sa[j][2] - mn1);
            Sa[j][3] = __expf(Sa[j][3] - mn1);
            sum0 += Sa[j][0] + Sa[j][1];
            sum1 += Sa[j][2] + Sa[j][3];
        }
        sum0 += __shfl_xor_sync(0xffffffff, sum0, 1);
        sum0 += __shfl_xor_sync(0xffffffff, sum0, 2);
        sum1 += __shfl_xor_sync(0xffffffff, sum1, 1);
        sum1 += __shfl_xor_sync(0xffffffff, sum1, 2);
        l[0] = l[0] * alpha0 + sum0;
        l[1] = l[1] * alpha1 + sum1;

#pragma unroll
        for (int nt = 0; nt < 16; nt++) {
            Oa[nt][0] *= alpha0; Oa[nt][1] *= alpha0;
            Oa[nt][2] *= alpha1; Oa[nt][3] *= alpha1;
        }

        // ---- P V (1-pass fp16) ----
        const uint32_t vBase = s0 + AVT + lrow * SVB + lkoff;
#pragma unroll
        for (int ks = 0; ks < 4; ks++) {
            uint32_t ph[4];
#pragma unroll
            for (int hf = 0; hf < 2; hf++) {
                const int j = 2 * ks + hf;
                __half2 h01 = __floats2half2_rn(Sa[j][0], Sa[j][1]);
                __half2 h23 = __floats2half2_rn(Sa[j][2], Sa[j][3]);
                ph[2*hf]     = *(uint32_t*)&h01;
                ph[2*hf + 1] = *(uint32_t*)&h23;
            }
#pragma unroll
            for (int nb = 0; nb < 8; nb++) {
                uint32_t vb[4];
                ldsm4(vb, vBase + nb * 16 * SVB + ks * 32);
                mma_f16(Oa[2*nb],   ph, vb[0], vb[2]);
                mma_f16(Oa[2*nb+1], ph, vb[1], vb[3]);
            }
        }
    }

    // ---- epilogue: normalize, write fp16 hi plane ----
    const float invl0 = 1.f / l[0];
    const float invl1 = 1.f / l[1];
    const int r0g = q0 + w * 16 + grp;
    const size_t row0 = (size_t)(b * SEQ + r0g) * DIM + h * HD;
    const size_t row1 = row0 + (size_t)8 * DIM;
#pragma unroll
    for (int nt = 0; nt < 16; nt++) {
        const int col = nt * 8 + tig * 2;
        float o0 = Oa[nt][0] * invl0, o1 = Oa[nt][1] * invl0;
        float o2 = Oa[nt][2] * invl1, o3 = Oa[nt][3] * invl1;
        *(__half2*)(Ohi + row0 + col) = __floats2half2_rn(o0, o1);
        *(__half2*)(Ohi + row1 + col) = __floats2half2_rn(o2, o3);
    }
}

// ---------------------------------------------------------------------------
extern "C" void kernel_launch(void* const* d_in, const int* in_sizes, int n_in,
                              void* d_out, int out_size)
{
    (void)in_sizes; (void)n_in; (void)out_size;
    const float* x  = (const float*)d_in[0];
    const float* Wq = (const float*)d_in[1];
    const float* Wk = (const float*)d_in[2];
    const float* Wv = (const float*)d_in[3];
    const float* Wo = (const float*)d_in[4];
    const float* bo = (const float*)d_in[5];
    float* out = (float*)d_out;

    float *q, *k;
    __half *xh, *ah, *w16, *qh, *kh, *vh;
    cudaGetSymbolAddress((void**)&q,   g_q);
    cudaGetSymbolAddress((void**)&k,   g_k);
    cudaGetSymbolAddress((void**)&xh,  g_xh);
    cudaGetSymbolAddress((void**)&ah,  g_ah);
    cudaGetSymbolAddress((void**)&w16, g_w16);
    cudaGetSymbolAddress((void**)&qh,  g_qh);
    cudaGetSymbolAddress((void**)&kh,  g_kh);
    cudaGetSymbolAddress((void**)&vh,  g_vh);

    const size_t WSZ = (size_t)DIM * DIM;
    const int nx4 = (MROWS * DIM) / 4;
    const int nw4 = (DIM * DIM) / 4;

    cvt16_kernel<<<nx4 / 256, 256>>>(x, xh, nx4);
    cvt16_kernel<<<nw4 / 256, 256>>>(Wq, w16 + 0 * WSZ, nw4);
    cvt16_kernel<<<nw4 / 256, 256>>>(Wk, w16 + 1 * WSZ, nw4);
    cvt16_kernel<<<nw4 / 256, 256>>>(Wv, w16 + 2 * WSZ, nw4);
    cvt16_kernel<<<nw4 / 256, 256>>>(Wo, w16 + 3 * WSZ, nw4);

    cudaFuncSetAttribute(gemm_mma_kernel<true>,
                         cudaFuncAttributeMaxDynamicSharedMemorySize, GSMEM);
    cudaFuncSetAttribute(gemm_mma_kernel<false>,
                         cudaFuncAttributeMaxDynamicSharedMemorySize, GSMEM);

    dim3 ggrid(DIM / 128, MROWS / 128);
    // Q, K: fp32 out (for RoPE; fp32 accumulator precision into the rope round)
    gemm_mma_kernel<false><<<ggrid, 256, GSMEM>>>(
        xh, w16 + 0 * WSZ, nullptr, q, nullptr, MROWS, DIM, DIM);
    gemm_mma_kernel<false><<<ggrid, 256, GSMEM>>>(
        xh, w16 + 1 * WSZ, nullptr, k, nullptr, MROWS, DIM, DIM);
    // V: fp16 out direct to vh
    gemm_mma_kernel<true><<<ggrid, 256, GSMEM>>>(
        xh, w16 + 2 * WSZ, nullptr, nullptr, vh, MROWS, DIM, DIM);

    int rope_threads = BATCH * SEQ * NHEAD * 64;
    rope_cvt16_kernel<<<rope_threads / 256, 256>>>(q, qh);
    rope_cvt16_kernel<<<rope_threads / 256, 256>>>(k, kh);

    cudaFuncSetAttribute(attn_mma_kernel,
                         cudaFuncAttributeMaxDynamicSharedMemorySize, ASMEM);
    attn_mma_kernel<<<dim3(SEQ / 128, BATCH * NHEAD), 256, ASMEM>>>(
        qh, kh, vh, ah);

    // Output projection: fp32 out with bias
    gemm_mma_kernel<false><<<ggrid, 256, GSMEM>>>(
        ah, w16 + 3 * WSZ, bo, out, nullptr, MROWS, DIM, DIM);
}

// round 14
// speedup vs baseline: 1.8713x; 1.0427x over previous
#include <cuda_runtime.h>
#include <cuda_fp16.h>
#include <math.h>
#include <stdint.h>

#define BATCH 4
#define SEQ   2048
#define DIM   2048
#define NHEAD 16
#define HD    128
#define MROWS (BATCH*SEQ)   // 8192

// ---------------- scratch (static device globals) ----------------
__device__ float g_q[(size_t)MROWS * DIM];
__device__ float g_k[(size_t)MROWS * DIM];
__device__ __half g_xh[(size_t)MROWS * DIM];
__device__ __half g_ah[(size_t)MROWS * DIM];
__device__ __half g_w16[4][(size_t)DIM * DIM];
__device__ __half g_qh[(size_t)MROWS * DIM];
__device__ __half g_kh[(size_t)MROWS * DIM];
__device__ __half g_vh[(size_t)MROWS * DIM];

// ---------------- low-level helpers ----------------
__device__ __forceinline__ uint32_t smem_u32(const void* p) {
    uint32_t a;
    asm("{ .reg .u64 t; cvta.to.shared.u64 t, %1; cvt.u32.u64 %0, t; }" : "=r"(a) : "l"(p));
    return a;
}
__device__ __forceinline__ void cp_async16(uint32_t s, const void* g) {
    asm volatile("cp.async.cg.shared.global [%0], [%1], 16;" :: "r"(s), "l"(g));
}
#define CP_COMMIT()  asm volatile("cp.async.commit_group;" ::: "memory")
#define CP_WAIT(n)   asm volatile("cp.async.wait_group %0;" :: "n"(n) : "memory")

__device__ __forceinline__ void ldsm4(uint32_t* r, uint32_t addr) {
    asm volatile("ldmatrix.sync.aligned.m8n8.x4.shared.b16 {%0,%1,%2,%3}, [%4];"
                 : "=r"(r[0]), "=r"(r[1]), "=r"(r[2]), "=r"(r[3]) : "r"(addr));
}
__device__ __forceinline__ void mma_f16(float* d, const uint32_t* a, uint32_t b0, uint32_t b1) {
    asm volatile(
        "mma.sync.aligned.m16n8k16.row.col.f32.f16.f16.f32 "
        "{%0,%1,%2,%3}, {%4,%5,%6,%7}, {%8,%9}, {%0,%1,%2,%3};"
        : "+f"(d[0]), "+f"(d[1]), "+f"(d[2]), "+f"(d[3])
        : "r"(a[0]), "r"(a[1]), "r"(a[2]), "r"(a[3]), "r"(b0), "r"(b1));
}

// ---------------------------------------------------------------------------
// fp32 -> fp16 round (single stream)
// ---------------------------------------------------------------------------
__global__ __launch_bounds__(256)
void cvt16_kernel(const float* __restrict__ src, __half* __restrict__ dst, int n4)
{
    int i = blockIdx.x * blockDim.x + threadIdx.x;
    if (i >= n4) return;
    float4 x = ((const float4*)src)[i];
    __half2 H0; H0.x = __float2half(x.x); H0.y = __float2half(x.y);
    __half2 H1; H1.x = __float2half(x.z); H1.y = __float2half(x.w);
    ((__half2*)dst)[i*2]   = H0;
    ((__half2*)dst)[i*2+1] = H1;
}

// fp32 -> fp16 round, 4 weight matrices in one launch (blockIdx.y selects)
__global__ __launch_bounds__(256)
void cvt16_w4_kernel(const float* __restrict__ s0, const float* __restrict__ s1,
                     const float* __restrict__ s2, const float* __restrict__ s3,
                     __half* __restrict__ dstbase, int n4)
{
    int i = blockIdx.x * blockDim.x + threadIdx.x;
    if (i >= n4) return;
    const int y = blockIdx.y;
    const float* src = (y == 0) ? s0 : (y == 1) ? s1 : (y == 2) ? s2 : s3;
    __half* dst = dstbase + (size_t)y * DIM * DIM;
    float4 x = ((const float4*)src)[i];
    __half2 H0; H0.x = __float2half(x.x); H0.y = __float2half(x.y);
    __half2 H1; H1.x = __float2half(x.z); H1.y = __float2half(x.w);
    ((__half2*)dst)[i*2]   = H0;
    ((__half2*)dst)[i*2+1] = H1;
}

// ---------------------------------------------------------------------------
// Fused RoPE + fp16 round; blockIdx.y picks (q->qh) or (k->kh)
// ---------------------------------------------------------------------------
__global__ __launch_bounds__(256)
void rope_cvt16_qk_kernel(const float* __restrict__ qsrc, __half* __restrict__ qdst,
                          const float* __restrict__ ksrc, __half* __restrict__ kdst)
{
    int idx = blockIdx.x * blockDim.x + threadIdx.x;
    const float* src = blockIdx.y ? ksrc : qsrc;
    __half* dst      = blockIdx.y ? kdst : qdst;
    int i = idx & 63;
    int h = (idx >> 6) & (NHEAD - 1);
    int s = (idx >> 10) & (SEQ - 1);
    int b = idx >> 21;

    float inv = expf(-9.210340371976184f * ((float)i * (1.0f / 64.0f)));
    float ang = (float)s * inv;
    float c, sn;
    sincosf(ang, &sn, &c);

    size_t base = (size_t)(b * SEQ + s) * DIM + h * HD;
    float t1 = src[base + i];
    float t2 = src[base + i + 64];
    dst[base + i]      = __float2half(t1 * c - t2 * sn);
    dst[base + i + 64] = __float2half(t2 * c + t1 * sn);
}

// ---------------------------------------------------------------------------
// fp16 1-pass GEMM core (shared by QKV-fused and O-projection kernels).
// CTA tile 128x128, BK=32, 8 warps, 3-stage cp.async pipeline, 2 CTA/SM.
// ---------------------------------------------------------------------------
#define GBK       32
#define ROW_B     80
#define PLANE_B   (128 * ROW_B)        // 10240
#define STAGE_B   (3 * PLANE_B)        // 30720 (Ah, [unused], Bh)
#define NSTAGE    3
#define GSMEM     (NSTAGE * STAGE_B)   // 92160

__device__ __forceinline__ void load_stage(uint32_t st_u32,
    const __half* __restrict__ Ah, const __half* __restrict__ Bh,
    int m0, int n0, int K, int kc, int tid)
{
#pragma unroll
    for (int p = 0; p < 3; p++) {
        if (p == 1) continue;
        const __half* src = (p == 0) ? Ah : Bh;
        const int rbase = (p == 0) ? m0 : n0;
#pragma unroll
        for (int i = 0; i < 2; i++) {
            int idx = i * 256 + tid;
            int r = idx >> 2, c = idx & 3;
            const void* g = src + (size_t)(rbase + r) * K + kc + c * 8;
            cp_async16(st_u32 + p * PLANE_B + r * ROW_B + c * 16, g);
        }
    }
}

// Mainloop producing acc[2][8][4]; returns nothing (acc by ref)
__device__ __forceinline__ void gemm_mainloop(
    float acc[2][8][4], const __half* __restrict__ Ah, const __half* __restrict__ Bh,
    int m0, int n0, int K, int tid, uint32_t sm0)
{
    const int wid  = tid >> 5;
    const int lane = tid & 31;
    const int wm   = wid & 3;
    const int wn   = wid >> 2;
    const int lrow  = lane & 15;
    const int lkoff = (lane >> 4) * 16;
    const int nchunk = K / GBK;

#pragma unroll
    for (int mt = 0; mt < 2; mt++)
#pragma unroll
        for (int nt = 0; nt < 8; nt++)
#pragma unroll
            for (int q = 0; q < 4; q++) acc[mt][nt][q] = 0.f;

    load_stage(sm0,           Ah, Bh, m0, n0, K, 0,   tid);
    CP_COMMIT();
    load_stage(sm0 + STAGE_B, Ah, Bh, m0, n0, K, GBK, tid);
    CP_COMMIT();

    for (int i = 0; i < nchunk; i++) {
        CP_WAIT(1);
        __syncthreads();

        if (i + 2 < nchunk)
            load_stage(sm0 + ((i + 2) % NSTAGE) * STAGE_B,
                       Ah, Bh, m0, n0, K, (i + 2) * GBK, tid);
        CP_COMMIT();

        const uint32_t st = sm0 + (i % NSTAGE) * STAGE_B;
        const uint32_t aRow = st + (wm * 32 + lrow) * ROW_B + lkoff;
        const uint32_t bRow = st + 2 * PLANE_B + (wn * 64 + lrow) * ROW_B + lkoff;

#pragma unroll
        for (int ks = 0; ks < 2; ks++) {
            uint32_t ah[2][4], bh[4][4];
#pragma unroll
            for (int mt = 0; mt < 2; mt++)
                ldsm4(ah[mt], aRow + mt * (16 * ROW_B) + ks * 32);
#pragma unroll
            for (int np = 0; np < 4; np++)
                ldsm4(bh[np], bRow + np * (16 * ROW_B) + ks * 32);
#pragma unroll
            for (int mt = 0; mt < 2; mt++)
#pragma unroll
                for (int nt = 0; nt < 8; nt++) {
                    const int np = nt >> 1, h = nt & 1;
                    mma_f16(acc[mt][nt], ah[mt], bh[np][h], bh[np][2 + h]);
                }
        }
        __syncthreads();
    }
}

// Fused Q/K/V projection: blockIdx.z selects weight + destination.
// z=0 -> q (fp32), z=1 -> k (fp32), z=2 -> vh (fp16)
__global__ __launch_bounds__(256, 2)
void gemm_qkv_kernel(const __half* __restrict__ Ah, const __half* __restrict__ Wbase,
                     float* __restrict__ q, float* __restrict__ k,
                     __half* __restrict__ vh, int M, int N, int K)
{
    extern __shared__ char smem[];
    const uint32_t sm0 = smem_u32(smem);
    const int tid = threadIdx.x;
    const int m0 = blockIdx.y * 128;
    const int n0 = blockIdx.x * 128;
    const int z  = blockIdx.z;
    const __half* Bh = Wbase + (size_t)z * N * K;

    float acc[2][8][4];
    gemm_mainloop(acc, Ah, Bh, m0, n0, K, tid, sm0);

    const int wid  = tid >> 5;
    const int lane = tid & 31;
    const int wm   = wid & 3;
    const int wn   = wid >> 2;
    const int grp  = lane >> 2;
    const int tig  = lane & 3;

#pragma unroll
    for (int mt = 0; mt < 2; mt++) {
        const int rbase = m0 + wm * 32 + mt * 16 + grp;
#pragma unroll
        for (int nt = 0; nt < 8; nt++) {
            const int col = n0 + wn * 64 + nt * 8 + tig * 2;
            float v00 = acc[mt][nt][0], v01 = acc[mt][nt][1];
            float v10 = acc[mt][nt][2], v11 = acc[mt][nt][3];
            if (z == 2) {
                *(__half2*)(vh + (size_t)rbase * N + col)       = __floats2half2_rn(v00, v01);
                *(__half2*)(vh + (size_t)(rbase + 8) * N + col) = __floats2half2_rn(v10, v11);
            } else {
                float* C = (z == 0) ? q : k;
                float2 v0; v0.x = v00; v0.y = v01;
                float2 v1; v1.x = v10; v1.y = v11;
                *(float2*)(C + (size_t)rbase * N + col)       = v0;
                *(float2*)(C + (size_t)(rbase + 8) * N + col) = v1;
            }
        }
    }
}

// Output projection: fp32 out with bias
__global__ __launch_bounds__(256, 2)
void gemm_o_kernel(const __half* __restrict__ Ah, const __half* __restrict__ Bh,
                   const float* __restrict__ bias, float* __restrict__ C,
                   int M, int N, int K)
{
    extern __shared__ char smem[];
    const uint32_t sm0 = smem_u32(smem);
    const int tid = threadIdx.x;
    const int m0 = blockIdx.y * 128;
    const int n0 = blockIdx.x * 128;

    float acc[2][8][4];
    gemm_mainloop(acc, Ah, Bh, m0, n0, K, tid, sm0);

    const int wid  = tid >> 5;
    const int lane = tid & 31;
    const int wm   = wid & 3;
    const int wn   = wid >> 2;
    const int grp  = lane >> 2;
    const int tig  = lane & 3;

#pragma unroll
    for (int mt = 0; mt < 2; mt++) {
        const int rbase = m0 + wm * 32 + mt * 16 + grp;
#pragma unroll
        for (int nt = 0; nt < 8; nt++) {
            const int col = n0 + wn * 64 + nt * 8 + tig * 2;
            float bx = bias[col], by = bias[col + 1];
            float2 v0; v0.x = acc[mt][nt][0] + bx; v0.y = acc[mt][nt][1] + by;
            float2 v1; v1.x = acc[mt][nt][2] + bx; v1.y = acc[mt][nt][3] + by;
            *(float2*)(C + (size_t)rbase * N + col)       = v0;
            *(float2*)(C + (size_t)(rbase + 8) * N + col) = v1;
        }
    }
}

// ---------------------------------------------------------------------------
// Causal flash attention, 1-pass fp16 (fp32 accumulate), now 2 CTA/SM.
// CTA: 128 q x 64 k per iter, 8 warps. Writes fp16 hi plane.
// ---------------------------------------------------------------------------
#define SKB 272            // Q/K smem row bytes (128 fp16 = 256B + 16 pad)
#define SVB 144            // Vt smem row bytes (64 fp16 = 128B + 16 pad)
#define AQH 0
#define AKH (AQH + 128*SKB)
#define AVT (AKH + 64*SKB)
#define ASMEM (AVT + 128*SVB)   // 70656

__global__ __launch_bounds__(256, 2)
void attn_mma_kernel(const __half* __restrict__ Qh, const __half* __restrict__ Kh,
                     const __half* __restrict__ Vh, __half* __restrict__ Ohi)
{
    extern __shared__ char smem[];
    const uint32_t s0 = smem_u32(smem);
    const int tid  = threadIdx.x;
    const int w    = tid >> 5;
    const int lane = tid & 31;
    const int grp  = lane >> 2;
    const int tig  = lane & 3;
    const int lrow  = lane & 15;
    const int lkoff = (lane >> 4) * 16;

    const int bh = blockIdx.y;
    const int b  = bh >> 4;
    const int h  = bh & (NHEAD - 1);
    const int qt = blockIdx.x;
    const int q0 = qt * 128;

    const size_t rowQ = (size_t)(b * SEQ + q0);
    const __half* qh_g = Qh + rowQ * DIM + h * HD;

    // Q tile -> smem
#pragma unroll
    for (int u = 0; u < 8; u++) {
        int idx = u * 256 + tid;
        int r = idx >> 4, c = idx & 15;
        cp_async16(s0 + AQH + r * SKB + c * 16, qh_g + (size_t)r * DIM + c * 8);
    }
    CP_COMMIT();

    float m[2] = {-1e30f, -1e30f};
    float l[2] = {0.f, 0.f};
    float Oa[16][4];
#pragma unroll
    for (int nt = 0; nt < 16; nt++)
#pragma unroll
        for (int q = 0; q < 4; q++) Oa[nt][q] = 0.f;

    const float scale = 0.08838834764831845f;
    const int nkt = 2 * qt + 2;

    for (int kt = 0; kt < nkt; kt++) {
        const int kv0 = kt * 64;
        const size_t rowK = (size_t)(b * SEQ + kv0);
        const __half* kh_g = Kh + rowK * DIM + h * HD;
        const __half* vh_g = Vh + rowK * DIM + h * HD;

        __syncthreads();

        // K tile
#pragma unroll
        for (int u = 0; u < 4; u++) {
            int idx = u * 256 + tid;
            int r = idx >> 4, c = idx & 15;
            cp_async16(s0 + AKH + r * SKB + c * 16, kh_g + (size_t)r * DIM + c * 8);
        }
        CP_COMMIT();

        // V tile transposed
#pragma unroll
        for (int u = 0; u < 4; u++) {
            int idx = u * 256 + tid;
            int kv = idx & 63, c = idx >> 6;
            uint4 xh = *(const uint4*)(vh_g + (size_t)kv * DIM + c * 8);
            const uint16_t* uh = (const uint16_t*)&xh;
#pragma unroll
            for (int j = 0; j < 8; j++)
                *(uint16_t*)(smem + AVT + (c * 8 + j) * SVB + kv * 2) = uh[j];
        }
        CP_WAIT(0);
        __syncthreads();

        // ---- S = Q K^T (1-pass fp16, fp32 acc) ----
        float Sa[8][4];
#pragma unroll
        for (int j = 0; j < 8; j++)
#pragma unroll
            for (int q = 0; q < 4; q++) Sa[j][q] = 0.f;

        const uint32_t aBase = s0 + AQH + (w * 16 + lrow) * SKB + lkoff;
        const uint32_t kBase = s0 + AKH + lrow * SKB + lkoff;
#pragma unroll
        for (int ks = 0; ks < 8; ks++) {
            uint32_t ah[4];
            ldsm4(ah, aBase + ks * 32);
#pragma unroll
            for (int p = 0; p < 4; p++) {
                uint32_t kb[4];
                ldsm4(kb, kBase + p * 16 * SKB + ks * 32);
                mma_f16(Sa[2*p],   ah, kb[0], kb[2]);
                mma_f16(Sa[2*p+1], ah, kb[1], kb[3]);
            }
        }

        // ---- scale + causal mask ----
        const int r0g = q0 + w * 16 + grp;
        const int r1g = r0g + 8;
        const bool need_mask = (kt >= 2 * qt);
#pragma unroll
        for (int j = 0; j < 8; j++) {
            const int c0 = kv0 + j * 8 + tig * 2;
            Sa[j][0] *= scale; Sa[j][1] *= scale;
            Sa[j][2] *= scale; Sa[j][3] *= scale;
            if (need_mask) {
                if (c0     > r0g) Sa[j][0] = -1e9f;
                if (c0 + 1 > r0g) Sa[j][1] = -1e9f;
                if (c0     > r1g) Sa[j][2] = -1e9f;
                if (c0 + 1 > r1g) Sa[j][3] = -1e9f;
            }
        }

        // ---- online softmax ----
        float mx0 = -1e30f, mx1 = -1e30f;
#pragma unroll
        for (int j = 0; j < 8; j++) {
            mx0 = fmaxf(mx0, fmaxf(Sa[j][0], Sa[j][1]));
            mx1 = fmaxf(mx1, fmaxf(Sa[j][2], Sa[j][3]));
        }
        mx0 = fmaxf(mx0, __shfl_xor_sync(0xffffffff, mx0, 1));
        mx0 = fmaxf(mx0, __shfl_xor_sync(0xffffffff, mx0, 2));
        mx1 = fmaxf(mx1, __shfl_xor_sync(0xffffffff, mx1, 1));
        mx1 = fmaxf(mx1, __shfl_xor_sync(0xffffffff, mx1, 2));

        const float mn0 = fmaxf(m[0], mx0);
        const float mn1 = fmaxf(m[1], mx1);
        const float alpha0 = __expf(m[0] - mn0);
        const float alpha1 = __expf(m[1] - mn1);
        m[0] = mn0; m[1] = mn1;

        float sum0 = 0.f, sum1 = 0.f;
#pragma unroll
        for (int j = 0; j < 8; j++) {
            Sa[j][0] = __expf(Sa[j][0] - mn0);
            Sa[j][1] = __expf(Sa[j][1] - mn0);
            Sa[j][2] = __expf(Sa[j][2] - mn1);
            Sa[j][3] = __expf(Sa[j][3] - mn1);
            sum0 += Sa[j][0] + Sa[j][1];
            sum1 += Sa[j][2] + Sa[j][3];
        }
        sum0 += __shfl_xor_sync(0xffffffff, sum0, 1);
        sum0 += __shfl_xor_sync(0xffffffff, sum0, 2);
        sum1 += __shfl_xor_sync(0xffffffff, sum1, 1);
        sum1 += __shfl_xor_sync(0xffffffff, sum1, 2);
        l[0] = l[0] * alpha0 + sum0;
        l[1] = l[1] * alpha1 + sum1;

#pragma unroll
        for (int nt = 0; nt < 16; nt++) {
            Oa[nt][0] *= alpha0; Oa[nt][1] *= alpha0;
            Oa[nt][2] *= alpha1; Oa[nt][3] *= alpha1;
        }

        // ---- P V (1-pass fp16) ----
        const uint32_t vBase = s0 + AVT + lrow * SVB + lkoff;
#pragma unroll
        for (int ks = 0; ks < 4; ks++) {
            uint32_t ph[4];
#pragma unroll
            for (int hf = 0; hf < 2; hf++) {
                const int j = 2 * ks + hf;
                __half2 h01 = __floats2half2_rn(Sa[j][0], Sa[j][1]);
                __half2 h23 = __floats2half2_rn(Sa[j][2], Sa[j][3]);
                ph[2*hf]     = *(uint32_t*)&h01;
                ph[2*hf + 1] = *(uint32_t*)&h23;
            }
#pragma unroll
            for (int nb = 0; nb < 8; nb++) {
                uint32_t vb[4];
                ldsm4(vb, vBase + nb * 16 * SVB + ks * 32);
                mma_f16(Oa[2*nb],   ph, vb[0], vb[2]);
                mma_f16(Oa[2*nb+1], ph, vb[1], vb[3]);
            }
        }
    }

    // ---- epilogue: normalize, write fp16 hi plane ----
    const float invl0 = 1.f / l[0];
    const float invl1 = 1.f / l[1];
    const int r0g = q0 + w * 16 + grp;
    const size_t row0 = (size_t)(b * SEQ + r0g) * DIM + h * HD;
    const size_t row1 = row0 + (size_t)8 * DIM;
#pragma unroll
    for (int nt = 0; nt < 16; nt++) {
        const int col = nt * 8 + tig * 2;
        float o0 = Oa[nt][0] * invl0, o1 = Oa[nt][1] * invl0;
        float o2 = Oa[nt][2] * invl1, o3 = Oa[nt][3] * invl1;
        *(__half2*)(Ohi + row0 + col) = __floats2half2_rn(o0, o1);
        *(__half2*)(Ohi + row1 + col) = __floats2half2_rn(o2, o3);
    }
}

// ---------------------------------------------------------------------------
extern "C" void kernel_launch(void* const* d_in, const int* in_sizes, int n_in,
                              void* d_out, int out_size)
{
    (void)in_sizes; (void)n_in; (void)out_size;
    const float* x  = (const float*)d_in[0];
    const float* Wq = (const float*)d_in[1];
    const float* Wk = (const float*)d_in[2];
    const float* Wv = (const float*)d_in[3];
    const float* Wo = (const float*)d_in[4];
    const float* bo = (const float*)d_in[5];
    float* out = (float*)d_out;

    float *q, *k;
    __half *xh, *ah, *w16, *qh, *kh, *vh;
    cudaGetSymbolAddress((void**)&q,   g_q);
    cudaGetSymbolAddress((void**)&k,   g_k);
    cudaGetSymbolAddress((void**)&xh,  g_xh);
    cudaGetSymbolAddress((void**)&ah,  g_ah);
    cudaGetSymbolAddress((void**)&w16, g_w16);
    cudaGetSymbolAddress((void**)&qh,  g_qh);
    cudaGetSymbolAddress((void**)&kh,  g_kh);
    cudaGetSymbolAddress((void**)&vh,  g_vh);

    const size_t WSZ = (size_t)DIM * DIM;
    const int nx4 = (MROWS * DIM) / 4;
    const int nw4 = (DIM * DIM) / 4;

    cvt16_kernel<<<nx4 / 256, 256>>>(x, xh, nx4);
    cvt16_w4_kernel<<<dim3(nw4 / 256, 4), 256>>>(Wq, Wk, Wv, Wo, w16, nw4);

    cudaFuncSetAttribute(gemm_qkv_kernel,
                         cudaFuncAttributeMaxDynamicSharedMemorySize, GSMEM);
    cudaFuncSetAttribute(gemm_o_kernel,
                         cudaFuncAttributeMaxDynamicSharedMemorySize, GSMEM);

    // Fused Q/K/V projection: one launch, grid.z = 3
    gemm_qkv_kernel<<<dim3(DIM / 128, MROWS / 128, 3), 256, GSMEM>>>(
        xh, w16, q, k, vh, MROWS, DIM, DIM);

    int rope_threads = BATCH * SEQ * NHEAD * 64;
    rope_cvt16_qk_kernel<<<dim3(rope_threads / 256, 2), 256>>>(q, qh, k, kh);

    cudaFuncSetAttribute(attn_mma_kernel,
                         cudaFuncAttributeMaxDynamicSharedMemorySize, ASMEM);
    attn_mma_kernel<<<dim3(SEQ / 128, BATCH * NHEAD), 256, ASMEM>>>(
        qh, kh, vh, ah);

    gemm_o_kernel<<<dim3(DIM / 128, MROWS / 128), 256, GSMEM>>>(
        ah, w16 + 3 * WSZ, bo, out, MROWS, DIM, DIM);
}

// round 16
// speedup vs baseline: 2.0704x; 1.1064x over previous
#include <cuda_runtime.h>
#include <cuda_fp16.h>
#include <math.h>
#include <stdint.h>

#define BATCH 4
#define SEQ   2048
#define DIM   2048
#define NHEAD 16
#define HD    128
#define MROWS (BATCH*SEQ)   // 8192

// ---------------- scratch (static device globals) ----------------
__device__ float g_q[(size_t)MROWS * DIM];
__device__ float g_k[(size_t)MROWS * DIM];
__device__ __half g_xh[(size_t)MROWS * DIM];
__device__ __half g_ah[(size_t)MROWS * DIM];
__device__ __half g_w16[4][(size_t)DIM * DIM];
__device__ __half g_qh[(size_t)MROWS * DIM];
__device__ __half g_kh[(size_t)MROWS * DIM];
__device__ __half g_vh[(size_t)MROWS * DIM];

// ---------------- low-level helpers ----------------
__device__ __forceinline__ uint32_t smem_u32(const void* p) {
    uint32_t a;
    asm("{ .reg .u64 t; cvta.to.shared.u64 t, %1; cvt.u32.u64 %0, t; }" : "=r"(a) : "l"(p));
    return a;
}
__device__ __forceinline__ void cp_async16(uint32_t s, const void* g) {
    asm volatile("cp.async.cg.shared.global [%0], [%1], 16;" :: "r"(s), "l"(g));
}
#define CP_COMMIT()  asm volatile("cp.async.commit_group;" ::: "memory")
#define CP_WAIT(n)   asm volatile("cp.async.wait_group %0;" :: "n"(n) : "memory")

__device__ __forceinline__ void ldsm4(uint32_t* r, uint32_t addr) {
    asm volatile("ldmatrix.sync.aligned.m8n8.x4.shared.b16 {%0,%1,%2,%3}, [%4];"
                 : "=r"(r[0]), "=r"(r[1]), "=r"(r[2]), "=r"(r[3]) : "r"(addr));
}
__device__ __forceinline__ void mma_f16(float* d, const uint32_t* a, uint32_t b0, uint32_t b1) {
    asm volatile(
        "mma.sync.aligned.m16n8k16.row.col.f32.f16.f16.f32 "
        "{%0,%1,%2,%3}, {%4,%5,%6,%7}, {%8,%9}, {%0,%1,%2,%3};"
        : "+f"(d[0]), "+f"(d[1]), "+f"(d[2]), "+f"(d[3])
        : "r"(a[0]), "r"(a[1]), "r"(a[2]), "r"(a[3]), "r"(b0), "r"(b1));
}

// ---------------------------------------------------------------------------
// fp32 -> fp16 round (single stream)
// ---------------------------------------------------------------------------
__global__ __launch_bounds__(256)
void cvt16_kernel(const float* __restrict__ src, __half* __restrict__ dst, int n4)
{
    int i = blockIdx.x * blockDim.x + threadIdx.x;
    if (i >= n4) return;
    float4 x = ((const float4*)src)[i];
    __half2 H0; H0.x = __float2half(x.x); H0.y = __float2half(x.y);
    __half2 H1; H1.x = __float2half(x.z); H1.y = __float2half(x.w);
    ((__half2*)dst)[i*2]   = H0;
    ((__half2*)dst)[i*2+1] = H1;
}

// fp32 -> fp16 round, 4 weight matrices in one launch (blockIdx.y selects)
__global__ __launch_bounds__(256)
void cvt16_w4_kernel(const float* __restrict__ s0, const float* __restrict__ s1,
                     const float* __restrict__ s2, const float* __restrict__ s3,
                     __half* __restrict__ dstbase, int n4)
{
    int i = blockIdx.x * blockDim.x + threadIdx.x;
    if (i >= n4) return;
    const int y = blockIdx.y;
    const float* src = (y == 0) ? s0 : (y == 1) ? s1 : (y == 2) ? s2 : s3;
    __half* dst = dstbase + (size_t)y * DIM * DIM;
    float4 x = ((const float4*)src)[i];
    __half2 H0; H0.x = __float2half(x.x); H0.y = __float2half(x.y);
    __half2 H1; H1.x = __float2half(x.z); H1.y = __float2half(x.w);
    ((__half2*)dst)[i*2]   = H0;
    ((__half2*)dst)[i*2+1] = H1;
}

// ---------------------------------------------------------------------------
// Fused RoPE: one thread rotates BOTH q and k (single sincosf/expf)
// ---------------------------------------------------------------------------
__global__ __launch_bounds__(256)
void rope_qk_kernel(const float* __restrict__ qsrc, __half* __restrict__ qdst,
                    const float* __restrict__ ksrc, __half* __restrict__ kdst)
{
    int idx = blockIdx.x * blockDim.x + threadIdx.x;
    int i = idx & 63;
    int h = (idx >> 6) & (NHEAD - 1);
    int s = (idx >> 10) & (SEQ - 1);
    int b = idx >> 21;

    float inv = expf(-9.210340371976184f * ((float)i * (1.0f / 64.0f)));
    float ang = (float)s * inv;
    float c, sn;
    sincosf(ang, &sn, &c);

    size_t base = (size_t)(b * SEQ + s) * DIM + h * HD;
    {
        float t1 = qsrc[base + i];
        float t2 = qsrc[base + i + 64];
        qdst[base + i]      = __float2half(t1 * c - t2 * sn);
        qdst[base + i + 64] = __float2half(t2 * c + t1 * sn);
    }
    {
        float t1 = ksrc[base + i];
        float t2 = ksrc[base + i + 64];
        kdst[base + i]      = __float2half(t1 * c - t2 * sn);
        kdst[base + i + 64] = __float2half(t2 * c + t1 * sn);
    }
}

// ---------------------------------------------------------------------------
// fp16 1-pass GEMM core. CTA tile 128x128, BK=64, 8 warps, 3-stage cp.async,
// 2 CTA/SM. Tight 2-plane stages (A,B), 144B rows (conflict-free ldmatrix).
// ---------------------------------------------------------------------------
#define GBK       64
#define ROW_B     144                  // 64 fp16 = 128B + 16 pad
#define PLANE_B   (128 * ROW_B)        // 18432
#define STAGE_B   (2 * PLANE_B)        // 36864 (A, B)
#define NSTAGE    3
#define GSMEM     (NSTAGE * STAGE_B)   // 110592 -> 2 CTA/SM = 216KB

__device__ __forceinline__ void load_stage(uint32_t st_u32,
    const __half* __restrict__ Ah, const __half* __restrict__ Bh,
    int m0, int n0, int K, int kc, int tid)
{
#pragma unroll
    for (int p = 0; p < 2; p++) {
        const __half* src = (p == 0) ? Ah : Bh;
        const int rbase = (p == 0) ? m0 : n0;
#pragma unroll
        for (int i = 0; i < 4; i++) {
            int idx = i * 256 + tid;
            int r = idx >> 3, c = idx & 7;
            const void* g = src + (size_t)(rbase + r) * K + kc + c * 8;
            cp_async16(st_u32 + p * PLANE_B + r * ROW_B + c * 16, g);
        }
    }
}

__device__ __forceinline__ void gemm_mainloop(
    float acc[2][8][4], const __half* __restrict__ Ah, const __half* __restrict__ Bh,
    int m0, int n0, int K, int tid, uint32_t sm0)
{
    const int wid  = tid >> 5;
    const int lane = tid & 31;
    const int wm   = wid & 3;
    const int wn   = wid >> 2;
    const int lrow  = lane & 15;
    const int lkoff = (lane >> 4) * 16;
    const int nchunk = K / GBK;

#pragma unroll
    for (int mt = 0; mt < 2; mt++)
#pragma unroll
        for (int nt = 0; nt < 8; nt++)
#pragma unroll
            for (int q = 0; q < 4; q++) acc[mt][nt][q] = 0.f;

    load_stage(sm0,           Ah, Bh, m0, n0, K, 0,   tid);
    CP_COMMIT();
    load_stage(sm0 + STAGE_B, Ah, Bh, m0, n0, K, GBK, tid);
    CP_COMMIT();

    for (int i = 0; i < nchunk; i++) {
        CP_WAIT(1);
        __syncthreads();

        if (i + 2 < nchunk)
            load_stage(sm0 + ((i + 2) % NSTAGE) * STAGE_B,
                       Ah, Bh, m0, n0, K, (i + 2) * GBK, tid);
        CP_COMMIT();

        const uint32_t st = sm0 + (i % NSTAGE) * STAGE_B;
        const uint32_t aRow = st + (wm * 32 + lrow) * ROW_B + lkoff;
        const uint32_t bRow = st + PLANE_B + (wn * 64 + lrow) * ROW_B + lkoff;

#pragma unroll
        for (int ks = 0; ks < 4; ks++) {
            uint32_t ah[2][4], bh[4][4];
#pragma unroll
            for (int mt = 0; mt < 2; mt++)
                ldsm4(ah[mt], aRow + mt * (16 * ROW_B) + ks * 32);
#pragma unroll
            for (int np = 0; np < 4; np++)
                ldsm4(bh[np], bRow + np * (16 * ROW_B) + ks * 32);
#pragma unroll
            for (int mt = 0; mt < 2; mt++)
#pragma unroll
                for (int nt = 0; nt < 8; nt++) {
                    const int np = nt >> 1, h = nt & 1;
                    mma_f16(acc[mt][nt], ah[mt], bh[np][h], bh[np][2 + h]);
                }
        }
        __syncthreads();
    }
}

// Fused Q/K/V projection: blockIdx.z selects weight + destination.
__global__ __launch_bounds__(256, 2)
void gemm_qkv_kernel(const __half* __restrict__ Ah, const __half* __restrict__ Wbase,
                     float* __restrict__ q, float* __restrict__ k,
                     __half* __restrict__ vh, int M, int N, int K)
{
    extern __shared__ char smem[];
    const uint32_t sm0 = smem_u32(smem);
    const int tid = threadIdx.x;
    const int m0 = blockIdx.y * 128;
    const int n0 = blockIdx.x * 128;
    const int z  = blockIdx.z;
    const __half* Bh = Wbase + (size_t)z * N * K;

    float acc[2][8][4];
    gemm_mainloop(acc, Ah, Bh, m0, n0, K, tid, sm0);

    const int wid  = tid >> 5;
    const int lane = tid & 31;
    const int wm   = wid & 3;
    const int wn   = wid >> 2;
    const int grp  = lane >> 2;
    const int tig  = lane & 3;

#pragma unroll
    for (int mt = 0; mt < 2; mt++) {
        const int rbase = m0 + wm * 32 + mt * 16 + grp;
#pragma unroll
        for (int nt = 0; nt < 8; nt++) {
            const int col = n0 + wn * 64 + nt * 8 + tig * 2;
            float v00 = acc[mt][nt][0], v01 = acc[mt][nt][1];
            float v10 = acc[mt][nt][2], v11 = acc[mt][nt][3];
            if (z == 2) {
                *(__half2*)(vh + (size_t)rbase * N + col)       = __floats2half2_rn(v00, v01);
                *(__half2*)(vh + (size_t)(rbase + 8) * N + col) = __floats2half2_rn(v10, v11);
            } else {
                float* C = (z == 0) ? q : k;
                float2 v0; v0.x = v00; v0.y = v01;
                float2 v1; v1.x = v10; v1.y = v11;
                *(float2*)(C + (size_t)rbase * N + col)       = v0;
                *(float2*)(C + (size_t)(rbase + 8) * N + col) = v1;
            }
        }
    }
}

// Output projection: fp32 out with bias
__global__ __launch_bounds__(256, 2)
void gemm_o_kernel(const __half* __restrict__ Ah, const __half* __restrict__ Bh,
                   const float* __restrict__ bias, float* __restrict__ C,
                   int M, int N, int K)
{
    extern __shared__ char smem[];
    const uint32_t sm0 = smem_u32(smem);
    const int tid = threadIdx.x;
    const int m0 = blockIdx.y * 128;
    const int n0 = blockIdx.x * 128;

    float acc[2][8][4];
    gemm_mainloop(acc, Ah, Bh, m0, n0, K, tid, sm0);

    const int wid  = tid >> 5;
    const int lane = tid & 31;
    const int wm   = wid & 3;
    const int wn   = wid >> 2;
    const int grp  = lane >> 2;
    const int tig  = lane & 3;

#pragma unroll
    for (int mt = 0; mt < 2; mt++) {
        const int rbase = m0 + wm * 32 + mt * 16 + grp;
#pragma unroll
        for (int nt = 0; nt < 8; nt++) {
            const int col = n0 + wn * 64 + nt * 8 + tig * 2;
            float bx = bias[col], by = bias[col + 1];
            float2 v0; v0.x = acc[mt][nt][0] + bx; v0.y = acc[mt][nt][1] + by;
            float2 v1; v1.x = acc[mt][nt][2] + bx; v1.y = acc[mt][nt][3] + by;
            *(float2*)(C + (size_t)rbase * N + col)       = v0;
            *(float2*)(C + (size_t)(rbase + 8) * N + col) = v1;
        }
    }
}

// ---------------------------------------------------------------------------
// Causal flash attention, 1-pass fp16 (fp32 accumulate), 2 CTA/SM,
// LPT scheduling: largest qt launches first.
// ---------------------------------------------------------------------------
#define SKB 272            // Q/K smem row bytes (128 fp16 = 256B + 16 pad)
#define SVB 144            // Vt smem row bytes (64 fp16 = 128B + 16 pad)
#define AQH 0
#define AKH (AQH + 128*SKB)
#define AVT (AKH + 64*SKB)
#define ASMEM (AVT + 128*SVB)   // 70656

__global__ __launch_bounds__(256, 2)
void attn_mma_kernel(const __half* __restrict__ Qh, const __half* __restrict__ Kh,
                     const __half* __restrict__ Vh, __half* __restrict__ Ohi)
{
    extern __shared__ char smem[];
    const uint32_t s0 = smem_u32(smem);
    const int tid  = threadIdx.x;
    const int w    = tid >> 5;
    const int lane = tid & 31;
    const int grp  = lane >> 2;
    const int tig  = lane & 3;
    const int lrow  = lane & 15;
    const int lkoff = (lane >> 4) * 16;

    const int bh = blockIdx.y;
    const int b  = bh >> 4;
    const int h  = bh & (NHEAD - 1);
    const int qt = gridDim.x - 1 - blockIdx.x;   // LPT: big tiles first
    const int q0 = qt * 128;

    const size_t rowQ = (size_t)(b * SEQ + q0);
    const __half* qh_g = Qh + rowQ * DIM + h * HD;

    // Q tile -> smem
#pragma unroll
    for (int u = 0; u < 8; u++) {
        int idx = u * 256 + tid;
        int r = idx >> 4, c = idx & 15;
        cp_async16(s0 + AQH + r * SKB + c * 16, qh_g + (size_t)r * DIM + c * 8);
    }
    CP_COMMIT();

    float m[2] = {-1e30f, -1e30f};
    float l[2] = {0.f, 0.f};
    float Oa[16][4];
#pragma unroll
    for (int nt = 0; nt < 16; nt++)
#pragma unroll
        for (int q = 0; q < 4; q++) Oa[nt][q] = 0.f;

    const float scale = 0.08838834764831845f;
    const int nkt = 2 * qt + 2;

    for (int kt = 0; kt < nkt; kt++) {
        const int kv0 = kt * 64;
        const size_t rowK = (size_t)(b * SEQ + kv0);
        const __half* kh_g = Kh + rowK * DIM + h * HD;
        const __half* vh_g = Vh + rowK * DIM + h * HD;

        __syncthreads();

        // K tile
#pragma unroll
        for (int u = 0; u < 4; u++) {
            int idx = u * 256 + tid;
            int r = idx >> 4, c = idx & 15;
            cp_async16(s0 + AKH + r * SKB + c * 16, kh_g + (size_t)r * DIM + c * 8);
        }
        CP_COMMIT();

        // V tile transposed
#pragma unroll
        for (int u = 0; u < 4; u++) {
            int idx = u * 256 + tid;
            int kv = idx & 63, c = idx >> 6;
            uint4 xh = *(const uint4*)(vh_g + (size_t)kv * DIM + c * 8);
            const uint16_t* uh = (const uint16_t*)&xh;
#pragma unroll
            for (int j = 0; j < 8; j++)
                *(uint16_t*)(smem + AVT + (c * 8 + j) * SVB + kv * 2) = uh[j];
        }
        CP_WAIT(0);
        __syncthreads();

        // ---- S = Q K^T ----
        float Sa[8][4];
#pragma unroll
        for (int j = 0; j < 8; j++)
#pragma unroll
            for (int q = 0; q < 4; q++) Sa[j][q] = 0.f;

        const uint32_t aBase = s0 + AQH + (w * 16 + lrow) * SKB + lkoff;
        const uint32_t kBase = s0 + AKH + lrow * SKB + lkoff;
#pragma unroll
        for (int ks = 0; ks < 8; ks++) {
            uint32_t ah[4];
            ldsm4(ah, aBase + ks * 32);
#pragma unroll
            for (int p = 0; p < 4; p++) {
                uint32_t kb[4];
                ldsm4(kb, kBase + p * 16 * SKB + ks * 32);
                mma_f16(Sa[2*p],   ah, kb[0], kb[2]);
                mma_f16(Sa[2*p+1], ah, kb[1], kb[3]);
            }
        }

        // ---- scale + causal mask ----
        const int r0g = q0 + w * 16 + grp;
        const int r1g = r0g + 8;
        const bool need_mask = (kt >= 2 * qt);
#pragma unroll
        for (int j = 0; j < 8; j++) {
            const int c0 = kv0 + j * 8 + tig * 2;
            Sa[j][0] *= scale; Sa[j][1] *= scale;
            Sa[j][2] *= scale; Sa[j][3] *= scale;
            if (need_mask) {
                if (c0     > r0g) Sa[j][0] = -1e9f;
                if (c0 + 1 > r0g) Sa[j][1] = -1e9f;
                if (c0     > r1g) Sa[j][2] = -1e9f;
                if (c0 + 1 > r1g) Sa[j][3] = -1e9f;
            }
        }

        // ---- online softmax ----
        float mx0 = -1e30f, mx1 = -1e30f;
#pragma unroll
        for (int j = 0; j < 8; j++) {
            mx0 = fmaxf(mx0, fmaxf(Sa[j][0], Sa[j][1]));
            mx1 = fmaxf(mx1, fmaxf(Sa[j][2], Sa[j][3]));
        }
        mx0 = fmaxf(mx0, __shfl_xor_sync(0xffffffff, mx0, 1));
        mx0 = fmaxf(mx0, __shfl_xor_sync(0xffffffff, mx0, 2));
        mx1 = fmaxf(mx1, __shfl_xor_sync(0xffffffff, mx1, 1));
        mx1 = fmaxf(mx1, __shfl_xor_sync(0xffffffff, mx1, 2));

        const float mn0 = fmaxf(m[0], mx0);
        const float mn1 = fmaxf(m[1], mx1);
        const float alpha0 = __expf(m[0] - mn0);
        const float alpha1 = __expf(m[1] - mn1);
        m[0] = mn0; m[1] = mn1;

        float sum0 = 0.f, sum1 = 0.f;
#pragma unroll
        for (int j = 0; j < 8; j++) {
            Sa[j][0] = __expf(Sa[j][0] - mn0);
            Sa[j][1] = __expf(Sa[j][1] - mn0);
            Sa[j][2] = __expf(Sa[j][2] - mn1);
            Sa[j][3] = __expf(Sa[j][3] - mn1);
            sum0 += Sa[j][0] + Sa[j][1];
            sum1 += Sa[j][2] + Sa[j][3];
        }
        sum0 += __shfl_xor_sync(0xffffffff, sum0, 1);
        sum0 += __shfl_xor_sync(0xffffffff, sum0, 2);
        sum1 += __shfl_xor_sync(0xffffffff, sum1, 1);
        sum1 += __shfl_xor_sync(0xffffffff, sum1, 2);
        l[0] = l[0] * alpha0 + sum0;
        l[1] = l[1] * alpha1 + sum1;

#pragma unroll
        for (int nt = 0; nt < 16; nt++) {
            Oa[nt][0] *= alpha0; Oa[nt][1] *= alpha0;
            Oa[nt][2] *= alpha1; Oa[nt][3] *= alpha1;
        }

        // ---- P V ----
        const uint32_t vBase = s0 + AVT + lrow * SVB + lkoff;
#pragma unroll
        for (int ks = 0; ks < 4; ks++) {
            uint32_t ph[4];
#pragma unroll
            for (int hf = 0; hf < 2; hf++) {
                const int j = 2 * ks + hf;
                __half2 h01 = __floats2half2_rn(Sa[j][0], Sa[j][1]);
                __half2 h23 = __floats2half2_rn(Sa[j][2], Sa[j][3]);
                ph[2*hf]     = *(uint32_t*)&h01;
                ph[2*hf + 1] = *(uint32_t*)&h23;
            }
#pragma unroll
            for (int nb = 0; nb < 8; nb++) {
                uint32_t vb[4];
                ldsm4(vb, vBase + nb * 16 * SVB + ks * 32);
                mma_f16(Oa[2*nb],   ph, vb[0], vb[2]);
                mma_f16(Oa[2*nb+1], ph, vb[1], vb[3]);
            }
        }
    }

    // ---- epilogue ----
    const float invl0 = 1.f / l[0];
    const float invl1 = 1.f / l[1];
    const int r0g = q0 + w * 16 + grp;
    const size_t row0 = (size_t)(b * SEQ + r0g) * DIM + h * HD;
    const size_t row1 = row0 + (size_t)8 * DIM;
#pragma unroll
    for (int nt = 0; nt < 16; nt++) {
        const int col = nt * 8 + tig * 2;
        float o0 = Oa[nt][0] * invl0, o1 = Oa[nt][1] * invl0;
        float o2 = Oa[nt][2] * invl1, o3 = Oa[nt][3] * invl1;
        *(__half2*)(Ohi + row0 + col) = __floats2half2_rn(o0, o1);
        *(__half2*)(Ohi + row1 + col) = __floats2half2_rn(o2, o3);
    }
}

// ---------------------------------------------------------------------------
extern "C" void kernel_launch(void* const* d_in, const int* in_sizes, int n_in,
                              void* d_out, int out_size)
{
    (void)in_sizes; (void)n_in; (void)out_size;
    const float* x  = (const float*)d_in[0];
    const float* Wq = (const float*)d_in[1];
    const float* Wk = (const float*)d_in[2];
    const float* Wv = (const float*)d_in[3];
    const float* Wo = (const float*)d_in[4];
    const float* bo = (const float*)d_in[5];
    float* out = (float*)d_out;

    float *q, *k;
    __half *xh, *ah, *w16, *qh, *kh, *vh;
    cudaGetSymbolAddress((void**)&q,   g_q);
    cudaGetSymbolAddress((void**)&k,   g_k);
    cudaGetSymbolAddress((void**)&xh,  g_xh);
    cudaGetSymbolAddress((void**)&ah,  g_ah);
    cudaGetSymbolAddress((void**)&w16, g_w16);
    cudaGetSymbolAddress((void**)&qh,  g_qh);
    cudaGetSymbolAddress((void**)&kh,  g_kh);
    cudaGetSymbolAddress((void**)&vh,  g_vh);

    const size_t WSZ = (size_t)DIM * DIM;
    const int nx4 = (MROWS * DIM) / 4;
    const int nw4 = (DIM * DIM) / 4;

    cvt16_kernel<<<nx4 / 256, 256>>>(x, xh, nx4);
    cvt16_w4_kernel<<<dim3(nw4 / 256, 4), 256>>>(Wq, Wk, Wv, Wo, w16, nw4);

    cudaFuncSetAttribute(gemm_qkv_kernel,
                         cudaFuncAttributeMaxDynamicSharedMemorySize, GSMEM);
    cudaFuncSetAttribute(gemm_o_kernel,
                         cudaFuncAttributeMaxDynamicSharedMemorySize, GSMEM);

    gemm_qkv_kernel<<<dim3(DIM / 128, MROWS / 128, 3), 256, GSMEM>>>(
        xh, w16, q, k, vh, MROWS, DIM, DIM);

    int rope_threads = BATCH * SEQ * NHEAD * 64;
    rope_qk_kernel<<<rope_threads / 256, 256>>>(q, qh, k, kh);

    cudaFuncSetAttribute(attn_mma_kernel,
                         cudaFuncAttributeMaxDynamicSharedMemorySize, ASMEM);
    attn_mma_kernel<<<dim3(SEQ / 128, BATCH * NHEAD), 256, ASMEM>>>(
        qh, kh, vh, ah);

    gemm_o_kernel<<<dim3(DIM / 128, MROWS / 128), 256, GSMEM>>>(
        ah, w16 + 3 * WSZ, bo, out, MROWS, DIM, DIM);
}